// round 13
// baseline (speedup 1.0000x reference)
#include <cuda_runtime.h>
#include <math.h>

#define BB 512
#define TT 200
#define NTOK (BB*TT)          // 102400
#define MIDQ 132
#define NOUTS (BB*(TT-1))     // 101888
#define NQ 10001

// ---------------- scratch (device globals; no allocation) ----------------
__device__ float g_TQ [NQ*192];
__device__ float g_HQ [NQ*MIDQ];
__device__ float g_Tc [201*192];
__device__ float g_Tit[101*192];
__device__ float g_Tut[101*192];
__device__ float g_Tnh[101*192];
__device__ float g_Tna[101*192];
__device__ float g_c0[192], g_s3[192];
__device__ float g_XP[NTOK*192];
__device__ float g_HS[NTOK*64];
__device__ float g_qdisc[NQ], g_qSqd[NQ];
__device__ int4  g_qcls[NQ];

typedef unsigned long long ull;

__device__ __forceinline__ float fsig(float x){ return __fdividef(1.f, 1.f + __expf(-x)); }
__device__ __forceinline__ float tanha(float x){ float y; asm("tanh.approx.f32 %0,%1;" : "=f"(y) : "f"(x)); return y; }
__device__ __forceinline__ float siga(float x){ return fmaf(0.5f, tanha(0.5f*x), 0.5f); }

__device__ __forceinline__ ull pack2(float lo, float hi){
  ull r; asm("mov.b64 %0, {%1,%2};" : "=l"(r) : "f"(lo), "f"(hi)); return r;
}
__device__ __forceinline__ void unpack2(ull v, float& lo, float& hi){
  asm("mov.b64 {%0,%1}, %2;" : "=f"(lo), "=f"(hi) : "l"(v));
}
__device__ __forceinline__ ull ffma2(ull a, ull b, ull c){
  ull d; asm("fma.rn.f32x2 %0, %1, %2, %3;" : "=l"(d) : "l"(a), "l"(b), "l"(c)); return d;
}
__device__ __forceinline__ void cpasync4(unsigned smem, const void* g){
  asm volatile("cp.async.ca.shared.global [%0], [%1], 4;" :: "r"(smem), "l"(g));
}

// ================= P0: fused tables + tq_gemm + hq ==========================
// blocks [0,606): tables; [606,763): TQ gemm; [763,842): HQ
__global__ void p0_kernel(const float* __restrict__ E_q, const float* __restrict__ E_c,
                          const float* __restrict__ E_it, const float* __restrict__ E_ut,
                          const float* __restrict__ E_nh,
                          const float* __restrict__ W_ih, const float* __restrict__ b_ih,
                          const float* __restrict__ W_fuse, const float* __restrict__ b_fuse,
                          const float* __restrict__ qd_W1, const float* __restrict__ qd_b1)
{
  extern __shared__ __align__(16) char ps[];
  int tid = threadIdx.x;
  int blk = blockIdx.x;

  if (blk < 606) {
    float* e_s  = (float*)ps;
    float* tmp_s = e_s + 64;
    int b = blk, g = tid;
    if (b < 201) {
      if (g < 64) e_s[g] = E_c[b*64+g];
      __syncthreads();
      if (g < 192) {
        float acc = 0.f;
        #pragma unroll 8
        for (int k = 0; k < 64; k++) acc = fmaf(W_ih[g*320+64+k], e_s[k], acc);
        g_Tc[b*192+g] = acc;
      }
    } else if (b < 302) {
      int u = b - 201;
      if (g < 64) e_s[g] = E_it[u*64+g];
      __syncthreads();
      if (g < 192) {
        float acc = 0.f;
        #pragma unroll 8
        for (int k = 0; k < 64; k++) acc = fmaf(W_ih[g*320+192+k], e_s[k], acc);
        g_Tit[u*192+g] = acc;
      }
    } else if (b < 605) {
      int which = (b-302)/101, u = (b-302)%101;
      const float* E = (which == 0) ? E_ut : E_nh;
      int off = which*64;
      if (g < 64) e_s[g] = E[u*64+g];
      __syncthreads();
      if (g < 64) {
        float acc = 0.f;
        #pragma unroll 8
        for (int k = 0; k < 64; k++) acc = fmaf(W_fuse[g*192+off+k], e_s[k], acc);
        tmp_s[g] = acc;
      }
      __syncthreads();
      if (g < 192) {
        float acc = 0.f;
        #pragma unroll 8
        for (int d = 0; d < 64; d++) acc = fmaf(W_ih[g*320+256+d], tmp_s[d], acc);
        float* dst = (which == 0) ? g_Tut : (which == 1) ? g_Tnh : g_Tna;
        dst[u*192+g] = acc;
      }
    } else {
      if (g < 192) {
        float acc = b_ih[g], s = 0.f;
        #pragma unroll 8
        for (int d = 0; d < 64; d++) {
          acc = fmaf(W_ih[g*320+256+d], b_fuse[d], acc);
          s += W_ih[g*320+128+d];
        }
        g_c0[g] = acc; g_s3[g] = s;
      }
    }
  } else if (blk < 763) {
    float* Xs  = (float*)ps;        // 32*65
    float* Wsm = Xs + 32*65;        // 32*193
    int tx = tid & 15, ty = tid >> 4;
    int m0 = (blk - 606) * 64;
    float acc[4][12];
    #pragma unroll
    for (int p = 0; p < 4; p++)
      #pragma unroll
      for (int u = 0; u < 12; u++) acc[p][u] = 0.f;

    for (int kb = 0; kb < 64; kb += 32) {
      for (int i = tid; i < 64*32; i += 256) {
        int m = i >> 5, kk = i & 31;
        int row = m0 + m;
        Xs[kk*65+m] = (row < NQ) ? E_q[row*64 + kb + kk] : 0.f;
      }
      for (int i = tid; i < 192*32; i += 256) {
        int nn = i >> 5, kk = i & 31;
        Wsm[kk*193+nn] = W_ih[nn*320 + kb + kk];
      }
      __syncthreads();
      #pragma unroll
      for (int kk = 0; kk < 32; kk++) {
        float a[4], bb[12];
        #pragma unroll
        for (int p = 0; p < 4; p++) a[p] = Xs[kk*65 + ty*4 + p];
        #pragma unroll
        for (int u = 0; u < 12; u++) bb[u] = Wsm[kk*193 + tx*12 + u];
        #pragma unroll
        for (int p = 0; p < 4; p++)
          #pragma unroll
          for (int u = 0; u < 12; u++) acc[p][u] = fmaf(a[p], bb[u], acc[p][u]);
      }
      __syncthreads();
    }
    #pragma unroll
    for (int p = 0; p < 4; p++) {
      int m = m0 + ty*4 + p;
      if (m < NQ) {
        #pragma unroll
        for (int u = 0; u < 12; u++) g_TQ[(size_t)m*192 + tx*12 + u] = acc[p][u];
      }
    }
  } else {
    float* tile = (float*)ps;       // 128*64
    ull w2[32]; float bv = 0.f;
    if (tid < MIDQ) {
      const ull* wr = (const ull*)(qd_W1 + tid*64);
      #pragma unroll
      for (int k = 0; k < 32; k++) w2[k] = wr[k];
      bv = qd_b1[tid];
    }
    int tok0 = (blk - 763) * 128;
    for (int i = tid; i < 128*16; i += 256) {
      int r = i >> 4, c = i & 15;
      int row = tok0 + r; if (row >= NQ) row = NQ-1;
      ((float4*)tile)[r*16 + c] = ((const float4*)(E_q + (size_t)row*64))[c];
    }
    __syncthreads();
    if (tid < MIDQ) {
      for (int r = 0; r < 128; r += 2) {
        if (tok0 + r >= NQ) break;
        const ulonglong2* ha = (const ulonglong2*)(tile + r*64);
        const ulonglong2* hb = (const ulonglong2*)(tile + (r+1)*64);
        ull a0=0ull,a1=0ull,b0=0ull,b1=0ull;
        #pragma unroll
        for (int i2 = 0; i2 < 16; i2++) {
          ulonglong2 pa = ha[i2], pb = hb[i2];
          a0 = ffma2(w2[2*i2],   pa.x, a0);
          a1 = ffma2(w2[2*i2+1], pa.y, a1);
          b0 = ffma2(w2[2*i2],   pb.x, b0);
          b1 = ffma2(w2[2*i2+1], pb.y, b1);
        }
        float p0,p1,p2,p3,q0,q1,q2,q3;
        unpack2(a0,p0,p1); unpack2(a1,p2,p3);
        unpack2(b0,q0,q1); unpack2(b1,q2,q3);
        g_HQ[(size_t)(tok0+r)*MIDQ + tid] = fmaxf(bv + (p0+p1)+(p2+p3), 0.f);
        if (tok0+r+1 < NQ)
          g_HQ[(size_t)(tok0+r+1)*MIDQ + tid] = fmaxf(bv + (q0+q1)+(q2+q3), 0.f);
      }
    }
  }
}

// ---------------- P1b: warp-per-question heads + TQ fold --------------------
__global__ void p1b_kernel(const float* __restrict__ E_q,
                           const float* __restrict__ qd_W2, const float* __restrict__ qd_b2,
                           const float* __restrict__ dc_W1, const float* __restrict__ dc_b1,
                           const float* __restrict__ dc_W2, const float* __restrict__ dc_b2,
                           const int* __restrict__ q2c, const int* __restrict__ q2cm)
{
  __shared__ float dc1s[64*33];
  int tid = threadIdx.x;
  for (int i = tid; i < 32*64; i += 256) { int l = i >> 6, k = i & 63; dc1s[k*33+l] = dc_W1[i]; }
  __syncthreads();
  int lane = tid & 31, wid = tid >> 5;
  int q = blockIdx.x*8 + wid;
  if (q >= NQ) return;

  float h0 = g_HQ[(size_t)q*MIDQ + lane];
  float h1 = g_HQ[(size_t)q*MIDQ + lane + 32];
  float h2 = g_HQ[(size_t)q*MIDQ + lane + 64];
  float h3 = g_HQ[(size_t)q*MIDQ + lane + 96];
  float h4 = (lane < 4) ? g_HQ[(size_t)q*MIDQ + lane + 128] : 0.f;

  int cR = 0, mR = 0;
  if (lane < 4) { cR = q2c[q*4+lane]; mR = q2cm[q*4+lane]; }
  int cls[4], msk[4];
  #pragma unroll
  for (int j = 0; j < 4; j++) { cls[j] = __shfl_sync(0xffffffffu, cR, j); msk[j] = __shfl_sync(0xffffffffu, mR, j); }

  float qd[4];
  #pragma unroll
  for (int j = 0; j < 4; j++) {
    const float* wr = qd_W2 + (size_t)cls[j]*MIDQ;
    float acc = h0*wr[lane] + h1*wr[lane+32] + h2*wr[lane+64] + h3*wr[lane+96];
    if (lane < 4) acc += h4*wr[lane+128];
    #pragma unroll
    for (int o = 16; o > 0; o >>= 1) acc += __shfl_xor_sync(0xffffffffu, acc, o);
    qd[j] = fsig(acc + qd_b2[cls[j]]);
  }

  float dacc = dc_b1[lane];
  #pragma unroll 8
  for (int k = 0; k < 64; k++) dacc = fmaf(dc1s[k*33+lane], E_q[q*64+k], dacc);
  float dv = dc_W2[lane]*fmaxf(dacc, 0.f);
  #pragma unroll
  for (int o = 16; o > 0; o >>= 1) dv += __shfl_xor_sync(0xffffffffu, dv, o);

  float w[4]; float srel = 1e-6f;
  #pragma unroll
  for (int j = 0; j < 4; j++) srel += qd[j]*(float)msk[j];
  #pragma unroll
  for (int j = 0; j < 4; j++) w[j] = qd[j]*(float)msk[j]/srel;
  float S = 0.f; int cl[4];
  #pragma unroll
  for (int j = 0; j < 4; j++) {
    int c = cls[j]; bool fl = (msk[j] != 0);
    for (int j2 = 0; j2 < j; j2++) if (msk[j2] != 0 && cls[j2] == c) fl = false;
    if (fl) { S += qd[j]; cl[j] = c; } else cl[j] = -1;
  }
  if (lane == 0) {
    g_qSqd[q] = S;
    g_qcls[q] = make_int4(cl[0], cl[1], cl[2], cl[3]);
    g_qdisc[q] = fsig(dv + dc_b2[0])*10.f;
  }

  #pragma unroll
  for (int g = 0; g < 6; g++) {
    int o = g*32 + lane;
    float v = g_TQ[(size_t)q*192 + o];
    #pragma unroll
    for (int j = 0; j < 4; j++) v = fmaf(w[j], g_Tc[cls[j]*192 + o], v);
    g_TQ[(size_t)q*192 + o] = v;
  }
}

// ---------------- P2: XP[n] = gather-sum of tables --------------------------
__global__ void xp_kernel(const int* __restrict__ qseq, const int* __restrict__ cseq,
                          const int* __restrict__ itseq, const int* __restrict__ utseq,
                          const int* __restrict__ nhseq, const int* __restrict__ naseq)
{
  __shared__ int qi[32], iti[32], uti[32], nhi[32], nai[32];
  __shared__ float cri[32];
  int tid = threadIdx.x;
  int n0 = blockIdx.x*32;
  int grp = tid >> 5, l = tid & 31;
  if (grp == 0) qi[l]  = qseq [n0+l];
  else if (grp == 1) cri[l] = (float)cseq[n0+l];
  else if (grp == 2) iti[l] = itseq[n0+l];
  else if (grp == 3) uti[l] = utseq[n0+l];
  else if (grp == 4) nhi[l] = nhseq[n0+l];
  else               nai[l] = naseq[n0+l];
  __syncthreads();

  int sub = tid/48, c4 = tid%48;
  float4 s3v = ((const float4*)g_s3)[c4];
  float4 c0v = ((const float4*)g_c0)[c4];
  const float4* TQ4  = (const float4*)g_TQ;
  const float4* Tit4 = (const float4*)g_Tit;
  const float4* Tut4 = (const float4*)g_Tut;
  const float4* Tnh4 = (const float4*)g_Tnh;
  const float4* Tna4 = (const float4*)g_Tna;

  for (int tl = sub; tl < 32; tl += 4) {
    int n = n0 + tl;
    float4 v  = TQ4 [(size_t)qi[tl]*48 + c4];
    float4 a  = Tit4[iti[tl]*48 + c4];
    float4 bu = Tut4[uti[tl]*48 + c4];
    float4 bh = Tnh4[nhi[tl]*48 + c4];
    float4 ba = Tna4[nai[tl]*48 + c4];
    float cr = cri[tl];
    float4 o;
    o.x = v.x + a.x + bu.x + bh.x + ba.x + cr*s3v.x + c0v.x;
    o.y = v.y + a.y + bu.y + bh.y + ba.y + cr*s3v.y + c0v.y;
    o.z = v.z + a.z + bu.z + bh.z + ba.z + cr*s3v.z + c0v.z;
    o.w = v.w + a.w + bu.w + bh.w + ba.w + cr*s3v.w + c0v.w;
    ((float4*)g_XP)[(size_t)n*48 + c4] = o;
  }
}

// ---------------- K4: GRU scan, 4 seq/block whole-row, cp.async ring --------
__global__ void __launch_bounds__(192, 1) gru_kernel(const float* __restrict__ W_hh,
                                                     const float* __restrict__ b_hh)
{
  __shared__ __align__(16) float h_s[4][64];
  __shared__ float gh_s[4][192];
  __shared__ float xp_s[4][4][192];     // [seq][ring][row]
  int r = threadIdx.x;
  int b0 = blockIdx.x*4;
  ull w2[32];
  const ull* wrow = (const ull*)W_hh + (size_t)r*32;
  #pragma unroll
  for (int i = 0; i < 32; i++) w2[i] = wrow[i];
  float bv = b_hh[r];
  if (r < 64) { h_s[0][r]=0.f; h_s[1][r]=0.f; h_s[2][r]=0.f; h_s[3][r]=0.f; }

  const float* xpp[4];
  float* hsp[4];
  unsigned smp[4];
  #pragma unroll
  for (int s = 0; s < 4; s++) {
    xpp[s] = g_XP + (size_t)(b0+s)*TT*192 + r;
    hsp[s] = g_HS + (size_t)(b0+s)*TT*64;
    smp[s] = (unsigned)__cvta_generic_to_shared(&xp_s[s][0][r]);
  }

  // prologue: groups for t = 0,1,2
  #pragma unroll
  for (int k = 0; k < 3; k++) {
    #pragma unroll
    for (int s = 0; s < 4; s++) cpasync4(smp[s] + k*192*4, xpp[s] + (size_t)k*192);
    asm volatile("cp.async.commit_group;" ::: "memory");
  }
  __syncthreads();

  // gate-role indices (threads 0..191 cover 256 gate elems in <=2 trips)
  int g0s = r >> 6,        g0e = r & 63;          // elems 0..191
  int g1  = r + 192;                              // elems 192..255 (r < 64 only)

  for (int t = 0; t < TT; t++) {
    asm volatile("cp.async.wait_group 2;" ::: "memory");
    {
      int tf = (t+3 < TT) ? t+3 : TT-1;
      int sl = (t+3) & 3;
      #pragma unroll
      for (int s = 0; s < 4; s++) cpasync4(smp[s] + sl*192*4, xpp[s] + (size_t)tf*192);
      asm volatile("cp.async.commit_group;" ::: "memory");
    }

    ull acc[4][4];
    #pragma unroll
    for (int s = 0; s < 4; s++)
      #pragma unroll
      for (int c = 0; c < 4; c++) acc[s][c] = 0ull;
    #pragma unroll
    for (int i = 0; i < 8; i++) {
      #pragma unroll
      for (int s = 0; s < 4; s++) {
        const ulonglong2* hp = (const ulonglong2*)h_s[s];
        ulonglong2 p = hp[2*i], q = hp[2*i+1];
        acc[s][0] = ffma2(w2[4*i+0], p.x, acc[s][0]);
        acc[s][1] = ffma2(w2[4*i+1], p.y, acc[s][1]);
        acc[s][2] = ffma2(w2[4*i+2], q.x, acc[s][2]);
        acc[s][3] = ffma2(w2[4*i+3], q.y, acc[s][3]);
      }
    }
    #pragma unroll
    for (int s = 0; s < 4; s++) {
      float s0,s1,s2,s3,s4,s5,s6,s7;
      unpack2(acc[s][0],s0,s1); unpack2(acc[s][1],s2,s3);
      unpack2(acc[s][2],s4,s5); unpack2(acc[s][3],s6,s7);
      gh_s[s][r] = bv + (((s0+s1)+(s2+s3)) + ((s4+s5)+(s6+s7)));
    }
    __syncthreads();   // gh ready + xp slot t landed for all
    {
      // first gate element (all 192 threads)
      const float* xc = xp_s[g0s][t & 3];
      const float* gh = gh_s[g0s];
      float rg = siga(xc[g0e]      + gh[g0e]);
      float zg = siga(xc[64+g0e]   + gh[64+g0e]);
      float ng = tanha(fmaf(rg, gh[128+g0e], xc[128+g0e]));
      float hnew = fmaf(zg, h_s[g0s][g0e] - ng, ng);
      h_s[g0s][g0e] = hnew;
      hsp[g0s][(size_t)t*64 + g0e] = hnew;
      // second gate element (threads 0..63 -> seq 3)
      if (r < 64) {
        int e = g1 & 63;
        const float* xc3 = xp_s[3][t & 3];
        const float* gh3 = gh_s[3];
        float rg3 = siga(xc3[e]      + gh3[e]);
        float zg3 = siga(xc3[64+e]   + gh3[64+e]);
        float ng3 = tanha(fmaf(rg3, gh3[128+e], xc3[128+e]));
        float hnew3 = fmaf(zg3, h_s[3][e] - ng3, ng3);
        h_s[3][e] = hnew3;
        hsp[3][(size_t)t*64 + e] = hnew3;
      }
    }
    __syncthreads();
  }
}

// ---------------- K5+K6 fused: HL + readout (256 thr, 3 blocks/SM) ----------
__global__ void __launch_bounds__(256, 3) fout_kernel(
                            const float* __restrict__ la_W1, const float* __restrict__ la_b1,
                            const float* __restrict__ la_W2, const float* __restrict__ la_b2,
                            const int* __restrict__ qseq, float* __restrict__ out)
{
  extern __shared__ __align__(16) char sm_[];
  float* Ws = (float*)sm_;                 // [k*132 + row], 64*132 floats
  float* bs = Ws + 64*132;                 // 132 floats (+2 pad)
  ull*   tp = (ull*)(bs + 134);            // [pair*66 + k], 32 pairs
  __shared__ int qv_s[64];                 // qseq[n0+1 .. n0+64]

  int tid = threadIdx.x, lane = tid & 31, wid = tid >> 5;
  int n0 = blockIdx.x * 64;

  if (tid < 64) {
    int idx = n0 + tid + 1; if (idx >= NTOK) idx = NTOK-1;
    qv_s[tid] = qseq[idx];
  }
  for (int i = tid; i < 132*64; i += 256) {
    int row = i >> 6, k = i & 63;
    Ws[k*132 + row] = la_W1[i];
  }
  if (tid < 132) bs[tid] = la_b1[tid];
  for (int i = tid; i < 64*16; i += 256) {
    int tok = i >> 4, c = i & 15;
    float4 v = ((const float4*)(g_HS + (size_t)(n0+tok)*64))[c];
    int p = tok >> 1, e = tok & 1;
    float* base = (float*)&tp[p*66 + 4*c];
    base[0+e] = v.x; base[2+e] = v.y; base[4+e] = v.z; base[6+e] = v.w;
  }
  __syncthreads();

  float b0 = bs[lane], b1v = bs[32+lane], b2v = bs[64+lane], b3v = bs[96+lane];
  float b4v = (lane < 4) ? bs[128+lane] : 0.f;
  ull acc[4][5];
  {
    ull p0=pack2(b0,b0), p1=pack2(b1v,b1v), p2=pack2(b2v,b2v), p3=pack2(b3v,b3v), p4=pack2(b4v,b4v);
    #pragma unroll
    for (int p = 0; p < 4; p++) { acc[p][0]=p0; acc[p][1]=p1; acc[p][2]=p2; acc[p][3]=p3; acc[p][4]=p4; }
  }
  int pbase = wid*4;
  #pragma unroll 4
  for (int k = 0; k < 64; k++) {
    float w0 = Ws[k*132 + lane];
    float w1 = Ws[k*132 + 32 + lane];
    float w2v = Ws[k*132 + 64 + lane];
    float w3 = Ws[k*132 + 96 + lane];
    float w4 = (lane < 4) ? Ws[k*132 + 128 + lane] : 0.f;
    ull d0=pack2(w0,w0), d1=pack2(w1,w1), d2=pack2(w2v,w2v), d3=pack2(w3,w3), d4=pack2(w4,w4);
    #pragma unroll
    for (int p = 0; p < 4; p++) {
      ull hd = tp[(pbase+p)*66 + k];
      acc[p][0] = ffma2(d0, hd, acc[p][0]);
      acc[p][1] = ffma2(d1, hd, acc[p][1]);
      acc[p][2] = ffma2(d2, hd, acc[p][2]);
      acc[p][3] = ffma2(d3, hd, acc[p][3]);
      acc[p][4] = ffma2(d4, hd, acc[p][4]);
    }
  }

  #pragma unroll
  for (int p = 0; p < 4; p++) {
    float va[5], vb[5];
    #pragma unroll
    for (int c = 0; c < 5; c++) {
      unpack2(acc[p][c], va[c], vb[c]);
      va[c] = fmaxf(va[c], 0.f);
      vb[c] = fmaxf(vb[c], 0.f);
    }
    #pragma unroll
    for (int e = 0; e < 2; e++) {
      int lt = (pbase + p)*2 + e;
      int n = n0 + lt;
      int bb = n / TT, it = n - bb*TT;
      if (it == TT-1) continue;
      float v0 = e ? vb[0] : va[0];
      float v1 = e ? vb[1] : va[1];
      float v2 = e ? vb[2] : va[2];
      float v3 = e ? vb[3] : va[3];
      float v4 = e ? vb[4] : va[4];

      int q = qv_s[lt];
      int4 c4 = g_qcls[q];
      int carr[4] = {c4.x, c4.y, c4.z, c4.w};
      float acc4[4];
      #pragma unroll
      for (int jj = 0; jj < 4; jj++) {
        int cc = (carr[jj] < 0) ? 0 : carr[jj];       // dummy row keeps loads uniform
        const float* w2r = la_W2 + (size_t)cc*MIDQ;
        float a = v0*w2r[lane] + v1*w2r[32+lane] + v2*w2r[64+lane] + v3*w2r[96+lane];
        if (lane < 4) a += v4*w2r[128+lane];
        acc4[jj] = a;
      }
      #pragma unroll
      for (int o = 16; o > 0; o >>= 1) {              // ILP-4 interleaved butterflies
        #pragma unroll
        for (int jj = 0; jj < 4; jj++) acc4[jj] += __shfl_xor_sync(0xffffffffu, acc4[jj], o);
      }
      if (lane == 0) {
        float S = 0.f;
        #pragma unroll
        for (int jj = 0; jj < 4; jj++)
          if (carr[jj] >= 0) S += fsig(acc4[jj] + la_b2[carr[jj]]);
        float sq = g_qSqd[q];
        float y = g_qdisc[q]*__fdividef(S - sq, sq + 1e-6f);
        out[bb*(TT-1) + it] = fsig(y);
      }
    }
  }
}

// ---------------- launcher --------------------------------------------------
extern "C" void kernel_launch(void* const* d_in, const int* in_sizes, int n_in,
                              void* d_out, int out_size)
{
  const float* E_q    = (const float*)d_in[0];
  const float* E_c    = (const float*)d_in[1];
  const float* E_it   = (const float*)d_in[2];
  const float* E_ut   = (const float*)d_in[3];
  const float* E_nh   = (const float*)d_in[4];
  const float* W_fuse = (const float*)d_in[5];
  const float* b_fuse = (const float*)d_in[6];
  const float* W_ih   = (const float*)d_in[7];
  const float* b_ih   = (const float*)d_in[8];
  const float* W_hh   = (const float*)d_in[9];
  const float* b_hh   = (const float*)d_in[10];
  const float* qd_W1  = (const float*)d_in[11];
  const float* qd_b1  = (const float*)d_in[12];
  const float* qd_W2  = (const float*)d_in[13];
  const float* qd_b2  = (const float*)d_in[14];
  const float* la_W1  = (const float*)d_in[15];
  const float* la_b1  = (const float*)d_in[16];
  const float* la_W2  = (const float*)d_in[17];
  const float* la_b2  = (const float*)d_in[18];
  const float* dc_W1  = (const float*)d_in[19];
  const float* dc_b1  = (const float*)d_in[20];
  const float* dc_W2  = (const float*)d_in[21];
  const float* dc_b2  = (const float*)d_in[22];

  int off = (in_sizes[23] > 1000000) ? 1 : 0;
  const int* qseq  = (const int*)d_in[23+off];
  const int* cseq  = (const int*)d_in[24+off];
  const int* itseq = (const int*)d_in[25+off];
  const int* utseq = (const int*)d_in[26+off];
  const int* nhseq = (const int*)d_in[27+off];
  const int* naseq = (const int*)d_in[28+off];
  const int* q2c   = (const int*)d_in[29+off];
  const int* q2cm  = (const int*)d_in[30+off];

  const int P0_SMEM = 33024;                          // max(tq 33024, hq 32768)
  const int FOUT_SMEM = (64*132 + 134)*4 + 32*66*8;   // 51224 bytes
  cudaFuncSetAttribute(fout_kernel, cudaFuncAttributeMaxDynamicSharedMemorySize, FOUT_SMEM);

  p0_kernel<<<842, 256, P0_SMEM>>>(E_q, E_c, E_it, E_ut, E_nh,
                                   W_ih, b_ih, W_fuse, b_fuse, qd_W1, qd_b1);
  p1b_kernel<<<(NQ+7)/8, 256>>>(E_q, qd_W2, qd_b2, dc_W1, dc_b1, dc_W2, dc_b2, q2c, q2cm);
  xp_kernel<<<NTOK/32, 192>>>(qseq, cseq, itseq, utseq, nhseq, naseq);
  gru_kernel<<<BB/4, 192>>>(W_hh, b_hh);         // launch #4 -> profiled
  fout_kernel<<<NTOK/64, 256, FOUT_SMEM>>>(la_W1, la_b1, la_W2, la_b2, qseq, (float*)d_out);
}

// round 14
// speedup vs baseline: 1.0794x; 1.0794x over previous
#include <cuda_runtime.h>
#include <math.h>

#define BB 512
#define TT 200
#define NTOK (BB*TT)          // 102400
#define MIDQ 132
#define NOUTS (BB*(TT-1))     // 101888
#define NQ 10001

// ---------------- scratch (device globals; no allocation) ----------------
__device__ float g_TQ [NQ*192];
__device__ float g_HQ [NQ*MIDQ];
__device__ float g_Tc [201*192];
__device__ float g_Tit[101*192];
__device__ float g_Tut[101*192];
__device__ float g_Tnh[101*192];
__device__ float g_Tna[101*192];
__device__ float g_c0[192], g_s3[192];
__device__ float g_XP[NTOK*192];
__device__ float g_HS[NTOK*64];
__device__ float g_qdisc[NQ], g_qSqd[NQ];
__device__ int4  g_qcls[NQ];

typedef unsigned long long ull;

__device__ __forceinline__ float fsig(float x){ return __fdividef(1.f, 1.f + __expf(-x)); }
__device__ __forceinline__ float tanha(float x){ float y; asm("tanh.approx.f32 %0,%1;" : "=f"(y) : "f"(x)); return y; }
__device__ __forceinline__ float siga(float x){ return fmaf(0.5f, tanha(0.5f*x), 0.5f); }

__device__ __forceinline__ ull pack2(float lo, float hi){
  ull r; asm("mov.b64 %0, {%1,%2};" : "=l"(r) : "f"(lo), "f"(hi)); return r;
}
__device__ __forceinline__ void unpack2(ull v, float& lo, float& hi){
  asm("mov.b64 {%0,%1}, %2;" : "=f"(lo), "=f"(hi) : "l"(v));
}
__device__ __forceinline__ ull ffma2(ull a, ull b, ull c){
  ull d; asm("fma.rn.f32x2 %0, %1, %2, %3;" : "=l"(d) : "l"(a), "l"(b), "l"(c)); return d;
}
__device__ __forceinline__ void cpasync4(unsigned smem, const void* g){
  asm volatile("cp.async.ca.shared.global [%0], [%1], 4;" :: "r"(smem), "l"(g));
}

// ================= P0: fused tables + tq_gemm + hq ==========================
// blocks [0,606): tables; [606,763): TQ gemm; [763,842): HQ
__global__ void p0_kernel(const float* __restrict__ E_q, const float* __restrict__ E_c,
                          const float* __restrict__ E_it, const float* __restrict__ E_ut,
                          const float* __restrict__ E_nh,
                          const float* __restrict__ W_ih, const float* __restrict__ b_ih,
                          const float* __restrict__ W_fuse, const float* __restrict__ b_fuse,
                          const float* __restrict__ qd_W1, const float* __restrict__ qd_b1)
{
  extern __shared__ __align__(16) char ps[];
  int tid = threadIdx.x;
  int blk = blockIdx.x;

  if (blk < 606) {
    float* e_s  = (float*)ps;
    float* tmp_s = e_s + 64;
    int b = blk, g = tid;
    if (b < 201) {
      if (g < 64) e_s[g] = E_c[b*64+g];
      __syncthreads();
      if (g < 192) {
        float acc = 0.f;
        #pragma unroll 8
        for (int k = 0; k < 64; k++) acc = fmaf(W_ih[g*320+64+k], e_s[k], acc);
        g_Tc[b*192+g] = acc;
      }
    } else if (b < 302) {
      int u = b - 201;
      if (g < 64) e_s[g] = E_it[u*64+g];
      __syncthreads();
      if (g < 192) {
        float acc = 0.f;
        #pragma unroll 8
        for (int k = 0; k < 64; k++) acc = fmaf(W_ih[g*320+192+k], e_s[k], acc);
        g_Tit[u*192+g] = acc;
      }
    } else if (b < 605) {
      int which = (b-302)/101, u = (b-302)%101;
      const float* E = (which == 0) ? E_ut : E_nh;
      int off = which*64;
      if (g < 64) e_s[g] = E[u*64+g];
      __syncthreads();
      if (g < 64) {
        float acc = 0.f;
        #pragma unroll 8
        for (int k = 0; k < 64; k++) acc = fmaf(W_fuse[g*192+off+k], e_s[k], acc);
        tmp_s[g] = acc;
      }
      __syncthreads();
      if (g < 192) {
        float acc = 0.f;
        #pragma unroll 8
        for (int d = 0; d < 64; d++) acc = fmaf(W_ih[g*320+256+d], tmp_s[d], acc);
        float* dst = (which == 0) ? g_Tut : (which == 1) ? g_Tnh : g_Tna;
        dst[u*192+g] = acc;
      }
    } else {
      if (g < 192) {
        float acc = b_ih[g], s = 0.f;
        #pragma unroll 8
        for (int d = 0; d < 64; d++) {
          acc = fmaf(W_ih[g*320+256+d], b_fuse[d], acc);
          s += W_ih[g*320+128+d];
        }
        g_c0[g] = acc; g_s3[g] = s;
      }
    }
  } else if (blk < 763) {
    float* Xs  = (float*)ps;        // 32*65
    float* Wsm = Xs + 32*65;        // 32*193
    int tx = tid & 15, ty = tid >> 4;
    int m0 = (blk - 606) * 64;
    float acc[4][12];
    #pragma unroll
    for (int p = 0; p < 4; p++)
      #pragma unroll
      for (int u = 0; u < 12; u++) acc[p][u] = 0.f;

    for (int kb = 0; kb < 64; kb += 32) {
      for (int i = tid; i < 64*32; i += 256) {
        int m = i >> 5, kk = i & 31;
        int row = m0 + m;
        Xs[kk*65+m] = (row < NQ) ? E_q[row*64 + kb + kk] : 0.f;
      }
      for (int i = tid; i < 192*32; i += 256) {
        int nn = i >> 5, kk = i & 31;
        Wsm[kk*193+nn] = W_ih[nn*320 + kb + kk];
      }
      __syncthreads();
      #pragma unroll
      for (int kk = 0; kk < 32; kk++) {
        float a[4], bb[12];
        #pragma unroll
        for (int p = 0; p < 4; p++) a[p] = Xs[kk*65 + ty*4 + p];
        #pragma unroll
        for (int u = 0; u < 12; u++) bb[u] = Wsm[kk*193 + tx*12 + u];
        #pragma unroll
        for (int p = 0; p < 4; p++)
          #pragma unroll
          for (int u = 0; u < 12; u++) acc[p][u] = fmaf(a[p], bb[u], acc[p][u]);
      }
      __syncthreads();
    }
    #pragma unroll
    for (int p = 0; p < 4; p++) {
      int m = m0 + ty*4 + p;
      if (m < NQ) {
        #pragma unroll
        for (int u = 0; u < 12; u++) g_TQ[(size_t)m*192 + tx*12 + u] = acc[p][u];
      }
    }
  } else {
    float* tile = (float*)ps;       // 128*64
    ull w2[32]; float bv = 0.f;
    if (tid < MIDQ) {
      const ull* wr = (const ull*)(qd_W1 + tid*64);
      #pragma unroll
      for (int k = 0; k < 32; k++) w2[k] = wr[k];
      bv = qd_b1[tid];
    }
    int tok0 = (blk - 763) * 128;
    for (int i = tid; i < 128*16; i += 256) {
      int r = i >> 4, c = i & 15;
      int row = tok0 + r; if (row >= NQ) row = NQ-1;
      ((float4*)tile)[r*16 + c] = ((const float4*)(E_q + (size_t)row*64))[c];
    }
    __syncthreads();
    if (tid < MIDQ) {
      for (int r = 0; r < 128; r += 2) {
        if (tok0 + r >= NQ) break;
        const ulonglong2* ha = (const ulonglong2*)(tile + r*64);
        const ulonglong2* hb = (const ulonglong2*)(tile + (r+1)*64);
        ull a0=0ull,a1=0ull,b0=0ull,b1=0ull;
        #pragma unroll
        for (int i2 = 0; i2 < 16; i2++) {
          ulonglong2 pa = ha[i2], pb = hb[i2];
          a0 = ffma2(w2[2*i2],   pa.x, a0);
          a1 = ffma2(w2[2*i2+1], pa.y, a1);
          b0 = ffma2(w2[2*i2],   pb.x, b0);
          b1 = ffma2(w2[2*i2+1], pb.y, b1);
        }
        float p0,p1,p2,p3,q0,q1,q2,q3;
        unpack2(a0,p0,p1); unpack2(a1,p2,p3);
        unpack2(b0,q0,q1); unpack2(b1,q2,q3);
        g_HQ[(size_t)(tok0+r)*MIDQ + tid] = fmaxf(bv + (p0+p1)+(p2+p3), 0.f);
        if (tok0+r+1 < NQ)
          g_HQ[(size_t)(tok0+r+1)*MIDQ + tid] = fmaxf(bv + (q0+q1)+(q2+q3), 0.f);
      }
    }
  }
}

// ---------------- P1b: warp-per-question heads + TQ fold (ILP-4 reduce) -----
__global__ void p1b_kernel(const float* __restrict__ E_q,
                           const float* __restrict__ qd_W2, const float* __restrict__ qd_b2,
                           const float* __restrict__ dc_W1, const float* __restrict__ dc_b1,
                           const float* __restrict__ dc_W2, const float* __restrict__ dc_b2,
                           const int* __restrict__ q2c, const int* __restrict__ q2cm)
{
  __shared__ float dc1s[64*33];
  int tid = threadIdx.x;
  for (int i = tid; i < 32*64; i += 256) { int l = i >> 6, k = i & 63; dc1s[k*33+l] = dc_W1[i]; }
  __syncthreads();
  int lane = tid & 31, wid = tid >> 5;
  int q = blockIdx.x*8 + wid;
  if (q >= NQ) return;

  float h0 = g_HQ[(size_t)q*MIDQ + lane];
  float h1 = g_HQ[(size_t)q*MIDQ + lane + 32];
  float h2 = g_HQ[(size_t)q*MIDQ + lane + 64];
  float h3 = g_HQ[(size_t)q*MIDQ + lane + 96];
  float h4 = (lane < 4) ? g_HQ[(size_t)q*MIDQ + lane + 128] : 0.f;

  int cR = 0, mR = 0;
  if (lane < 4) { cR = q2c[q*4+lane]; mR = q2cm[q*4+lane]; }
  int cls[4], msk[4];
  #pragma unroll
  for (int j = 0; j < 4; j++) { cls[j] = __shfl_sync(0xffffffffu, cR, j); msk[j] = __shfl_sync(0xffffffffu, mR, j); }

  // 4 class-dots, butterflies interleaved (ILP-4)
  float accj[4];
  #pragma unroll
  for (int j = 0; j < 4; j++) {
    const float* wr = qd_W2 + (size_t)cls[j]*MIDQ;
    float a = h0*wr[lane] + h1*wr[lane+32] + h2*wr[lane+64] + h3*wr[lane+96];
    if (lane < 4) a += h4*wr[lane+128];
    accj[j] = a;
  }
  // disc head partial too (5th chain)
  float dacc = dc_b1[lane];
  #pragma unroll 8
  for (int k = 0; k < 64; k++) dacc = fmaf(dc1s[k*33+lane], E_q[q*64+k], dacc);
  float dv = dc_W2[lane]*fmaxf(dacc, 0.f);
  #pragma unroll
  for (int o = 16; o > 0; o >>= 1) {
    #pragma unroll
    for (int j = 0; j < 4; j++) accj[j] += __shfl_xor_sync(0xffffffffu, accj[j], o);
    dv += __shfl_xor_sync(0xffffffffu, dv, o);
  }
  float qd[4];
  #pragma unroll
  for (int j = 0; j < 4; j++) qd[j] = fsig(accj[j] + qd_b2[cls[j]]);

  float w[4]; float srel = 1e-6f;
  #pragma unroll
  for (int j = 0; j < 4; j++) srel += qd[j]*(float)msk[j];
  #pragma unroll
  for (int j = 0; j < 4; j++) w[j] = qd[j]*(float)msk[j]/srel;
  float S = 0.f; int cl[4];
  #pragma unroll
  for (int j = 0; j < 4; j++) {
    int c = cls[j]; bool fl = (msk[j] != 0);
    for (int j2 = 0; j2 < j; j2++) if (msk[j2] != 0 && cls[j2] == c) fl = false;
    if (fl) { S += qd[j]; cl[j] = c; } else cl[j] = -1;
  }
  if (lane == 0) {
    g_qSqd[q] = S;
    g_qcls[q] = make_int4(cl[0], cl[1], cl[2], cl[3]);
    g_qdisc[q] = fsig(dv + dc_b2[0])*10.f;
  }

  #pragma unroll
  for (int g = 0; g < 6; g++) {
    int o = g*32 + lane;
    float v = g_TQ[(size_t)q*192 + o];
    #pragma unroll
    for (int j = 0; j < 4; j++) v = fmaf(w[j], g_Tc[cls[j]*192 + o], v);
    g_TQ[(size_t)q*192 + o] = v;
  }
}

// ---------------- P2: XP[n] = gather-sum of tables --------------------------
__global__ void xp_kernel(const int* __restrict__ qseq, const int* __restrict__ cseq,
                          const int* __restrict__ itseq, const int* __restrict__ utseq,
                          const int* __restrict__ nhseq, const int* __restrict__ naseq)
{
  __shared__ int qi[32], iti[32], uti[32], nhi[32], nai[32];
  __shared__ float cri[32];
  int tid = threadIdx.x;
  int n0 = blockIdx.x*32;
  int grp = tid >> 5, l = tid & 31;
  if (grp == 0) qi[l]  = qseq [n0+l];
  else if (grp == 1) cri[l] = (float)cseq[n0+l];
  else if (grp == 2) iti[l] = itseq[n0+l];
  else if (grp == 3) uti[l] = utseq[n0+l];
  else if (grp == 4) nhi[l] = nhseq[n0+l];
  else               nai[l] = naseq[n0+l];
  __syncthreads();

  int sub = tid/48, c4 = tid%48;
  float4 s3v = ((const float4*)g_s3)[c4];
  float4 c0v = ((const float4*)g_c0)[c4];
  const float4* TQ4  = (const float4*)g_TQ;
  const float4* Tit4 = (const float4*)g_Tit;
  const float4* Tut4 = (const float4*)g_Tut;
  const float4* Tnh4 = (const float4*)g_Tnh;
  const float4* Tna4 = (const float4*)g_Tna;

  for (int tl = sub; tl < 32; tl += 4) {
    int n = n0 + tl;
    float4 v  = TQ4 [(size_t)qi[tl]*48 + c4];
    float4 a  = Tit4[iti[tl]*48 + c4];
    float4 bu = Tut4[uti[tl]*48 + c4];
    float4 bh = Tnh4[nhi[tl]*48 + c4];
    float4 ba = Tna4[nai[tl]*48 + c4];
    float cr = cri[tl];
    float4 o;
    o.x = v.x + a.x + bu.x + bh.x + ba.x + cr*s3v.x + c0v.x;
    o.y = v.y + a.y + bu.y + bh.y + ba.y + cr*s3v.y + c0v.y;
    o.z = v.z + a.z + bu.z + bh.z + ba.z + cr*s3v.z + c0v.z;
    o.w = v.w + a.w + bu.w + bh.w + ba.w + cr*s3v.w + c0v.w;
    ((float4*)g_XP)[(size_t)n*48 + c4] = o;
  }
}

// ---------------- K4: GRU scan, 2 seq/block, cp.async xp pipeline (R11) -----
__global__ void __launch_bounds__(192, 2) gru_kernel(const float* __restrict__ W_hh,
                                                     const float* __restrict__ b_hh)
{
  __shared__ __align__(16) float h_s[2][64];
  __shared__ float gh_s[2][192];
  __shared__ float xp_s[2][4][192];     // [seq][ring][row]
  int r = threadIdx.x;
  int bA = blockIdx.x*2, bBv = bA + 1;
  ull w2[32];
  const ull* wrow = (const ull*)W_hh + (size_t)r*32;
  #pragma unroll
  for (int i = 0; i < 32; i++) w2[i] = wrow[i];
  float bv = b_hh[r];
  if (r < 64) { h_s[0][r] = 0.f; h_s[1][r] = 0.f; }
  const float* xpA = g_XP + (size_t)bA*TT*192 + r;
  const float* xpB = g_XP + (size_t)bBv*TT*192 + r;
  float* hsA = g_HS + (size_t)bA*TT*64;
  float* hsB = g_HS + (size_t)bBv*TT*64;
  unsigned smA = (unsigned)__cvta_generic_to_shared(&xp_s[0][0][r]);
  unsigned smB = (unsigned)__cvta_generic_to_shared(&xp_s[1][0][r]);

  // prologue: issue groups for t = 0,1,2
  #pragma unroll
  for (int k = 0; k < 3; k++) {
    cpasync4(smA + k*192*4, xpA + (size_t)k*192);
    cpasync4(smB + k*192*4, xpB + (size_t)k*192);
    asm volatile("cp.async.commit_group;" ::: "memory");
  }
  __syncthreads();   // h_s visibility

  for (int t = 0; t < TT; t++) {
    asm volatile("cp.async.wait_group 2;" ::: "memory");   // group t landed

    // issue group for t+3 into slot (t+3)&3 (last read at t-1, barrier-safe)
    {
      int tf = (t+3 < TT) ? t+3 : TT-1;
      int sl = (t+3) & 3;
      cpasync4(smA + sl*192*4, xpA + (size_t)tf*192);
      cpasync4(smB + sl*192*4, xpB + (size_t)tf*192);
      asm volatile("cp.async.commit_group;" ::: "memory");
    }

    ull aA0=0ull,aA1=0ull,aA2=0ull,aA3=0ull;
    ull aB0=0ull,aB1=0ull,aB2=0ull,aB3=0ull;
    const ulonglong2* hA = (const ulonglong2*)h_s[0];
    const ulonglong2* hB = (const ulonglong2*)h_s[1];
    #pragma unroll
    for (int i = 0; i < 8; i++) {
      ulonglong2 pA = hA[2*i], qA = hA[2*i+1];
      ulonglong2 pB = hB[2*i], qB = hB[2*i+1];
      aA0 = ffma2(w2[4*i+0], pA.x, aA0);
      aB0 = ffma2(w2[4*i+0], pB.x, aB0);
      aA1 = ffma2(w2[4*i+1], pA.y, aA1);
      aB1 = ffma2(w2[4*i+1], pB.y, aB1);
      aA2 = ffma2(w2[4*i+2], qA.x, aA2);
      aB2 = ffma2(w2[4*i+2], qB.x, aB2);
      aA3 = ffma2(w2[4*i+3], qA.y, aA3);
      aB3 = ffma2(w2[4*i+3], qB.y, aB3);
    }
    {
      float s0,s1,s2,s3,s4,s5,s6,s7;
      unpack2(aA0,s0,s1); unpack2(aA1,s2,s3); unpack2(aA2,s4,s5); unpack2(aA3,s6,s7);
      gh_s[0][r] = bv + (((s0+s1)+(s2+s3)) + ((s4+s5)+(s6+s7)));
      unpack2(aB0,s0,s1); unpack2(aB1,s2,s3); unpack2(aB2,s4,s5); unpack2(aB3,s6,s7);
      gh_s[1][r] = bv + (((s0+s1)+(s2+s3)) + ((s4+s5)+(s6+s7)));
    }
    __syncthreads();   // gh ready + xp slot t visible to all
    if (r < 128) {
      int s = r >> 6, e = r & 63;
      const float* xc = xp_s[s][t & 3];
      const float* gh = gh_s[s];
      float rg = siga(xc[e]      + gh[e]);
      float zg = siga(xc[64+e]   + gh[64+e]);
      float ng = tanha(fmaf(rg, gh[128+e], xc[128+e]));
      float hnew = fmaf(zg, h_s[s][e] - ng, ng);
      h_s[s][e] = hnew;
      float* hso = s ? hsB : hsA;
      hso[(size_t)t*64 + e] = hnew;
    }
    __syncthreads();   // h ready for next matvec; xp slot reads done
  }
}

// ---------------- K5+K6 fused: HL + readout (2 tiles/block) -----------------
__global__ void __launch_bounds__(256, 3) fout_kernel(
                            const float* __restrict__ la_W1, const float* __restrict__ la_b1,
                            const float* __restrict__ la_W2, const float* __restrict__ la_b2,
                            const int* __restrict__ qseq, float* __restrict__ out)
{
  extern __shared__ __align__(16) char sm_[];
  float* Ws = (float*)sm_;                 // [k*132 + row], 64*132 floats
  float* bs = Ws + 64*132;                 // 132 floats (+2 pad)
  ull*   tp = (ull*)(bs + 134);            // [pair*66 + k], 32 pairs
  __shared__ int qv_s[64];

  int tid = threadIdx.x, lane = tid & 31, wid = tid >> 5;

  for (int i = tid; i < 132*64; i += 256) {
    int row = i >> 6, k = i & 63;
    Ws[k*132 + row] = la_W1[i];
  }
  if (tid < 132) bs[tid] = la_b1[tid];
  int pbase = wid*4;

  for (int tile = 0; tile < 2; tile++) {
    int n0 = blockIdx.x * 128 + tile * 64;
    __syncthreads();   // Ws ready (tile0) / previous epilogue done reading tp,qv_s
    if (tid < 64) {
      int idx = n0 + tid + 1; if (idx >= NTOK) idx = NTOK-1;
      qv_s[tid] = qseq[idx];
    }
    for (int i = tid; i < 64*16; i += 256) {
      int tok = i >> 4, c = i & 15;
      float4 v = ((const float4*)(g_HS + (size_t)(n0+tok)*64))[c];
      int p = tok >> 1, e = tok & 1;
      float* base = (float*)&tp[p*66 + 4*c];
      base[0+e] = v.x; base[2+e] = v.y; base[4+e] = v.z; base[6+e] = v.w;
    }
    __syncthreads();

    float b0 = bs[lane], b1v = bs[32+lane], b2v = bs[64+lane], b3v = bs[96+lane];
    float b4v = (lane < 4) ? bs[128+lane] : 0.f;
    ull acc[4][5];
    {
      ull p0=pack2(b0,b0), p1=pack2(b1v,b1v), p2=pack2(b2v,b2v), p3=pack2(b3v,b3v), p4=pack2(b4v,b4v);
      #pragma unroll
      for (int p = 0; p < 4; p++) { acc[p][0]=p0; acc[p][1]=p1; acc[p][2]=p2; acc[p][3]=p3; acc[p][4]=p4; }
    }
    #pragma unroll 4
    for (int k = 0; k < 64; k++) {
      float w0 = Ws[k*132 + lane];
      float w1 = Ws[k*132 + 32 + lane];
      float w2v = Ws[k*132 + 64 + lane];
      float w3 = Ws[k*132 + 96 + lane];
      float w4 = (lane < 4) ? Ws[k*132 + 128 + lane] : 0.f;
      ull d0=pack2(w0,w0), d1=pack2(w1,w1), d2=pack2(w2v,w2v), d3=pack2(w3,w3), d4=pack2(w4,w4);
      #pragma unroll
      for (int p = 0; p < 4; p++) {
        ull hd = tp[(pbase+p)*66 + k];
        acc[p][0] = ffma2(d0, hd, acc[p][0]);
        acc[p][1] = ffma2(d1, hd, acc[p][1]);
        acc[p][2] = ffma2(d2, hd, acc[p][2]);
        acc[p][3] = ffma2(d3, hd, acc[p][3]);
        acc[p][4] = ffma2(d4, hd, acc[p][4]);
      }
    }

    #pragma unroll
    for (int p = 0; p < 4; p++) {
      float va[5], vb[5];
      #pragma unroll
      for (int c = 0; c < 5; c++) {
        unpack2(acc[p][c], va[c], vb[c]);
        va[c] = fmaxf(va[c], 0.f);
        vb[c] = fmaxf(vb[c], 0.f);
      }
      #pragma unroll
      for (int e = 0; e < 2; e++) {
        int lt = (pbase + p)*2 + e;
        int n = n0 + lt;
        int bb = n / TT, it = n - bb*TT;
        if (it == TT-1) continue;
        float v0 = e ? vb[0] : va[0];
        float v1 = e ? vb[1] : va[1];
        float v2 = e ? vb[2] : va[2];
        float v3 = e ? vb[3] : va[3];
        float v4 = e ? vb[4] : va[4];

        int q = qv_s[lt];
        int4 c4 = g_qcls[q];
        int carr[4] = {c4.x, c4.y, c4.z, c4.w};
        float acc4[4];
        #pragma unroll
        for (int jj = 0; jj < 4; jj++) {
          int cc = (carr[jj] < 0) ? 0 : carr[jj];
          const float* w2r = la_W2 + (size_t)cc*MIDQ;
          float a = v0*w2r[lane] + v1*w2r[32+lane] + v2*w2r[64+lane] + v3*w2r[96+lane];
          if (lane < 4) a += v4*w2r[128+lane];
          acc4[jj] = a;
        }
        #pragma unroll
        for (int o = 16; o > 0; o >>= 1) {
          #pragma unroll
          for (int jj = 0; jj < 4; jj++) acc4[jj] += __shfl_xor_sync(0xffffffffu, acc4[jj], o);
        }
        if (lane == 0) {
          float S = 0.f;
          #pragma unroll
          for (int jj = 0; jj < 4; jj++)
            if (carr[jj] >= 0) S += fsig(acc4[jj] + la_b2[carr[jj]]);
          float sq = g_qSqd[q];
          float y = g_qdisc[q]*__fdividef(S - sq, sq + 1e-6f);
          out[bb*(TT-1) + it] = fsig(y);
        }
      }
    }
  }
}

// ---------------- launcher --------------------------------------------------
extern "C" void kernel_launch(void* const* d_in, const int* in_sizes, int n_in,
                              void* d_out, int out_size)
{
  const float* E_q    = (const float*)d_in[0];
  const float* E_c    = (const float*)d_in[1];
  const float* E_it   = (const float*)d_in[2];
  const float* E_ut   = (const float*)d_in[3];
  const float* E_nh   = (const float*)d_in[4];
  const float* W_fuse = (const float*)d_in[5];
  const float* b_fuse = (const float*)d_in[6];
  const float* W_ih   = (const float*)d_in[7];
  const float* b_ih   = (const float*)d_in[8];
  const float* W_hh   = (const float*)d_in[9];
  const float* b_hh   = (const float*)d_in[10];
  const float* qd_W1  = (const float*)d_in[11];
  const float* qd_b1  = (const float*)d_in[12];
  const float* qd_W2  = (const float*)d_in[13];
  const float* qd_b2  = (const float*)d_in[14];
  const float* la_W1  = (const float*)d_in[15];
  const float* la_b1  = (const float*)d_in[16];
  const float* la_W2  = (const float*)d_in[17];
  const float* la_b2  = (const float*)d_in[18];
  const float* dc_W1  = (const float*)d_in[19];
  const float* dc_b1  = (const float*)d_in[20];
  const float* dc_W2  = (const float*)d_in[21];
  const float* dc_b2  = (const float*)d_in[22];

  int off = (in_sizes[23] > 1000000) ? 1 : 0;
  const int* qseq  = (const int*)d_in[23+off];
  const int* cseq  = (const int*)d_in[24+off];
  const int* itseq = (const int*)d_in[25+off];
  const int* utseq = (const int*)d_in[26+off];
  const int* nhseq = (const int*)d_in[27+off];
  const int* naseq = (const int*)d_in[28+off];
  const int* q2c   = (const int*)d_in[29+off];
  const int* q2cm  = (const int*)d_in[30+off];

  const int P0_SMEM = 33024;                          // max(tq 33024, hq 32768)
  const int FOUT_SMEM = (64*132 + 134)*4 + 32*66*8;   // 51224 bytes
  cudaFuncSetAttribute(fout_kernel, cudaFuncAttributeMaxDynamicSharedMemorySize, FOUT_SMEM);

  p0_kernel<<<842, 256, P0_SMEM>>>(E_q, E_c, E_it, E_ut, E_nh,
                                   W_ih, b_ih, W_fuse, b_fuse, qd_W1, qd_b1);
  p1b_kernel<<<(NQ+7)/8, 256>>>(E_q, qd_W2, qd_b2, dc_W1, dc_b1, dc_W2, dc_b2, q2c, q2cm);
  xp_kernel<<<NTOK/32, 192>>>(qseq, cseq, itseq, utseq, nhseq, naseq);
  gru_kernel<<<BB/2, 192>>>(W_hh, b_hh);         // launch #4 -> profiled
  fout_kernel<<<NTOK/128, 256, FOUT_SMEM>>>(la_W1, la_b1, la_W2, la_b2, qseq, (float*)d_out);
}

// round 15
// speedup vs baseline: 1.2108x; 1.1217x over previous
#include <cuda_runtime.h>
#include <math.h>

#define BB 512
#define TT 200
#define NTOK (BB*TT)          // 102400
#define MIDQ 132
#define NOUTS (BB*(TT-1))     // 101888
#define NQ 10001

// ---------------- scratch (device globals; no allocation) ----------------
__device__ float g_TQ [NQ*192];
__device__ float g_HQ [NQ*MIDQ];
__device__ float g_Tc [201*192];
__device__ float g_Tit[101*192];
__device__ float g_Tut[101*192];
__device__ float g_Tnh[101*192];
__device__ float g_Tna[101*192];
__device__ float g_c0[192], g_s3[192];
__device__ float g_XP[NTOK*192];
__device__ float g_HS[NTOK*64];
__device__ float g_qdisc[NQ], g_qSqd[NQ];
__device__ int4  g_qcls[NQ];

typedef unsigned long long ull;

__device__ __forceinline__ float fsig(float x){ return __fdividef(1.f, 1.f + __expf(-x)); }
__device__ __forceinline__ float tanha(float x){ float y; asm("tanh.approx.f32 %0,%1;" : "=f"(y) : "f"(x)); return y; }
__device__ __forceinline__ float siga(float x){ return fmaf(0.5f, tanha(0.5f*x), 0.5f); }

__device__ __forceinline__ ull pack2(float lo, float hi){
  ull r; asm("mov.b64 %0, {%1,%2};" : "=l"(r) : "f"(lo), "f"(hi)); return r;
}
__device__ __forceinline__ void unpack2(ull v, float& lo, float& hi){
  asm("mov.b64 {%0,%1}, %2;" : "=f"(lo), "=f"(hi) : "l"(v));
}
__device__ __forceinline__ ull ffma2(ull a, ull b, ull c){
  ull d; asm("fma.rn.f32x2 %0, %1, %2, %3;" : "=l"(d) : "l"(a), "l"(b), "l"(c)); return d;
}
__device__ __forceinline__ void cpasync4(unsigned smem, const void* g){
  asm volatile("cp.async.ca.shared.global [%0], [%1], 4;" :: "r"(smem), "l"(g));
}

// ================= P0: fused tables + tq_gemm + hq ==========================
// blocks [0,606): tables; [606,763): TQ gemm; [763,842): HQ
__global__ void p0_kernel(const float* __restrict__ E_q, const float* __restrict__ E_c,
                          const float* __restrict__ E_it, const float* __restrict__ E_ut,
                          const float* __restrict__ E_nh,
                          const float* __restrict__ W_ih, const float* __restrict__ b_ih,
                          const float* __restrict__ W_fuse, const float* __restrict__ b_fuse,
                          const float* __restrict__ qd_W1, const float* __restrict__ qd_b1)
{
  extern __shared__ __align__(16) char ps[];
  int tid = threadIdx.x;
  int blk = blockIdx.x;

  if (blk < 606) {
    float* e_s  = (float*)ps;
    float* tmp_s = e_s + 64;
    int b = blk, g = tid;
    if (b < 201) {
      if (g < 64) e_s[g] = E_c[b*64+g];
      __syncthreads();
      if (g < 192) {
        float acc = 0.f;
        #pragma unroll 8
        for (int k = 0; k < 64; k++) acc = fmaf(W_ih[g*320+64+k], e_s[k], acc);
        g_Tc[b*192+g] = acc;
      }
    } else if (b < 302) {
      int u = b - 201;
      if (g < 64) e_s[g] = E_it[u*64+g];
      __syncthreads();
      if (g < 192) {
        float acc = 0.f;
        #pragma unroll 8
        for (int k = 0; k < 64; k++) acc = fmaf(W_ih[g*320+192+k], e_s[k], acc);
        g_Tit[u*192+g] = acc;
      }
    } else if (b < 605) {
      int which = (b-302)/101, u = (b-302)%101;
      const float* E = (which == 0) ? E_ut : E_nh;
      int off = which*64;
      if (g < 64) e_s[g] = E[u*64+g];
      __syncthreads();
      if (g < 64) {
        float acc = 0.f;
        #pragma unroll 8
        for (int k = 0; k < 64; k++) acc = fmaf(W_fuse[g*192+off+k], e_s[k], acc);
        tmp_s[g] = acc;
      }
      __syncthreads();
      if (g < 192) {
        float acc = 0.f;
        #pragma unroll 8
        for (int d = 0; d < 64; d++) acc = fmaf(W_ih[g*320+256+d], tmp_s[d], acc);
        float* dst = (which == 0) ? g_Tut : (which == 1) ? g_Tnh : g_Tna;
        dst[u*192+g] = acc;
      }
    } else {
      if (g < 192) {
        float acc = b_ih[g], s = 0.f;
        #pragma unroll 8
        for (int d = 0; d < 64; d++) {
          acc = fmaf(W_ih[g*320+256+d], b_fuse[d], acc);
          s += W_ih[g*320+128+d];
        }
        g_c0[g] = acc; g_s3[g] = s;
      }
    }
  } else if (blk < 763) {
    float* Xs  = (float*)ps;        // 32*65
    float* Wsm = Xs + 32*65;        // 32*193
    int tx = tid & 15, ty = tid >> 4;
    int m0 = (blk - 606) * 64;
    float acc[4][12];
    #pragma unroll
    for (int p = 0; p < 4; p++)
      #pragma unroll
      for (int u = 0; u < 12; u++) acc[p][u] = 0.f;

    for (int kb = 0; kb < 64; kb += 32) {
      for (int i = tid; i < 64*32; i += 256) {
        int m = i >> 5, kk = i & 31;
        int row = m0 + m;
        Xs[kk*65+m] = (row < NQ) ? E_q[row*64 + kb + kk] : 0.f;
      }
      for (int i = tid; i < 192*32; i += 256) {
        int nn = i >> 5, kk = i & 31;
        Wsm[kk*193+nn] = W_ih[nn*320 + kb + kk];
      }
      __syncthreads();
      #pragma unroll
      for (int kk = 0; kk < 32; kk++) {
        float a[4], bb[12];
        #pragma unroll
        for (int p = 0; p < 4; p++) a[p] = Xs[kk*65 + ty*4 + p];
        #pragma unroll
        for (int u = 0; u < 12; u++) bb[u] = Wsm[kk*193 + tx*12 + u];
        #pragma unroll
        for (int p = 0; p < 4; p++)
          #pragma unroll
          for (int u = 0; u < 12; u++) acc[p][u] = fmaf(a[p], bb[u], acc[p][u]);
      }
      __syncthreads();
    }
    #pragma unroll
    for (int p = 0; p < 4; p++) {
      int m = m0 + ty*4 + p;
      if (m < NQ) {
        #pragma unroll
        for (int u = 0; u < 12; u++) g_TQ[(size_t)m*192 + tx*12 + u] = acc[p][u];
      }
    }
  } else {
    float* tile = (float*)ps;       // 128*64
    ull w2[32]; float bv = 0.f;
    if (tid < MIDQ) {
      const ull* wr = (const ull*)(qd_W1 + tid*64);
      #pragma unroll
      for (int k = 0; k < 32; k++) w2[k] = wr[k];
      bv = qd_b1[tid];
    }
    int tok0 = (blk - 763) * 128;
    for (int i = tid; i < 128*16; i += 256) {
      int r = i >> 4, c = i & 15;
      int row = tok0 + r; if (row >= NQ) row = NQ-1;
      ((float4*)tile)[r*16 + c] = ((const float4*)(E_q + (size_t)row*64))[c];
    }
    __syncthreads();
    if (tid < MIDQ) {
      for (int r = 0; r < 128; r += 2) {
        if (tok0 + r >= NQ) break;
        const ulonglong2* ha = (const ulonglong2*)(tile + r*64);
        const ulonglong2* hb = (const ulonglong2*)(tile + (r+1)*64);
        ull a0=0ull,a1=0ull,b0=0ull,b1=0ull;
        #pragma unroll
        for (int i2 = 0; i2 < 16; i2++) {
          ulonglong2 pa = ha[i2], pb = hb[i2];
          a0 = ffma2(w2[2*i2],   pa.x, a0);
          a1 = ffma2(w2[2*i2+1], pa.y, a1);
          b0 = ffma2(w2[2*i2],   pb.x, b0);
          b1 = ffma2(w2[2*i2+1], pb.y, b1);
        }
        float p0,p1,p2,p3,q0,q1,q2,q3;
        unpack2(a0,p0,p1); unpack2(a1,p2,p3);
        unpack2(b0,q0,q1); unpack2(b1,q2,q3);
        g_HQ[(size_t)(tok0+r)*MIDQ + tid] = fmaxf(bv + (p0+p1)+(p2+p3), 0.f);
        if (tok0+r+1 < NQ)
          g_HQ[(size_t)(tok0+r+1)*MIDQ + tid] = fmaxf(bv + (q0+q1)+(q2+q3), 0.f);
      }
    }
  }
}

// ---------------- P1b: warp-per-question heads + TQ fold --------------------
__global__ void p1b_kernel(const float* __restrict__ E_q,
                           const float* __restrict__ qd_W2, const float* __restrict__ qd_b2,
                           const float* __restrict__ dc_W1, const float* __restrict__ dc_b1,
                           const float* __restrict__ dc_W2, const float* __restrict__ dc_b2,
                           const int* __restrict__ q2c, const int* __restrict__ q2cm)
{
  __shared__ float dc1s[64*33];
  int tid = threadIdx.x;
  for (int i = tid; i < 32*64; i += 256) { int l = i >> 6, k = i & 63; dc1s[k*33+l] = dc_W1[i]; }
  __syncthreads();
  int lane = tid & 31, wid = tid >> 5;
  int q = blockIdx.x*8 + wid;
  if (q >= NQ) return;

  float h0 = g_HQ[(size_t)q*MIDQ + lane];
  float h1 = g_HQ[(size_t)q*MIDQ + lane + 32];
  float h2 = g_HQ[(size_t)q*MIDQ + lane + 64];
  float h3 = g_HQ[(size_t)q*MIDQ + lane + 96];
  float h4 = (lane < 4) ? g_HQ[(size_t)q*MIDQ + lane + 128] : 0.f;

  int cR = 0, mR = 0;
  if (lane < 4) { cR = q2c[q*4+lane]; mR = q2cm[q*4+lane]; }
  int cls[4], msk[4];
  #pragma unroll
  for (int j = 0; j < 4; j++) { cls[j] = __shfl_sync(0xffffffffu, cR, j); msk[j] = __shfl_sync(0xffffffffu, mR, j); }

  float qd[4];
  #pragma unroll
  for (int j = 0; j < 4; j++) {
    const float* wr = qd_W2 + (size_t)cls[j]*MIDQ;
    float acc = h0*wr[lane] + h1*wr[lane+32] + h2*wr[lane+64] + h3*wr[lane+96];
    if (lane < 4) acc += h4*wr[lane+128];
    #pragma unroll
    for (int o = 16; o > 0; o >>= 1) acc += __shfl_xor_sync(0xffffffffu, acc, o);
    qd[j] = fsig(acc + qd_b2[cls[j]]);
  }

  float dacc = dc_b1[lane];
  #pragma unroll 8
  for (int k = 0; k < 64; k++) dacc = fmaf(dc1s[k*33+lane], E_q[q*64+k], dacc);
  float dv = dc_W2[lane]*fmaxf(dacc, 0.f);
  #pragma unroll
  for (int o = 16; o > 0; o >>= 1) dv += __shfl_xor_sync(0xffffffffu, dv, o);

  float w[4]; float srel = 1e-6f;
  #pragma unroll
  for (int j = 0; j < 4; j++) srel += qd[j]*(float)msk[j];
  #pragma unroll
  for (int j = 0; j < 4; j++) w[j] = qd[j]*(float)msk[j]/srel;
  float S = 0.f; int cl[4];
  #pragma unroll
  for (int j = 0; j < 4; j++) {
    int c = cls[j]; bool fl = (msk[j] != 0);
    for (int j2 = 0; j2 < j; j2++) if (msk[j2] != 0 && cls[j2] == c) fl = false;
    if (fl) { S += qd[j]; cl[j] = c; } else cl[j] = -1;
  }
  if (lane == 0) {
    g_qSqd[q] = S;
    g_qcls[q] = make_int4(cl[0], cl[1], cl[2], cl[3]);
    g_qdisc[q] = fsig(dv + dc_b2[0])*10.f;
  }

  #pragma unroll
  for (int g = 0; g < 6; g++) {
    int o = g*32 + lane;
    float v = g_TQ[(size_t)q*192 + o];
    #pragma unroll
    for (int j = 0; j < 4; j++) v = fmaf(w[j], g_Tc[cls[j]*192 + o], v);
    g_TQ[(size_t)q*192 + o] = v;
  }
}

// ---------------- P2: XP[n] = gather-sum of tables --------------------------
__global__ void xp_kernel(const int* __restrict__ qseq, const int* __restrict__ cseq,
                          const int* __restrict__ itseq, const int* __restrict__ utseq,
                          const int* __restrict__ nhseq, const int* __restrict__ naseq)
{
  __shared__ int qi[32], iti[32], uti[32], nhi[32], nai[32];
  __shared__ float cri[32];
  int tid = threadIdx.x;
  int n0 = blockIdx.x*32;
  int grp = tid >> 5, l = tid & 31;
  if (grp == 0) qi[l]  = qseq [n0+l];
  else if (grp == 1) cri[l] = (float)cseq[n0+l];
  else if (grp == 2) iti[l] = itseq[n0+l];
  else if (grp == 3) uti[l] = utseq[n0+l];
  else if (grp == 4) nhi[l] = nhseq[n0+l];
  else               nai[l] = naseq[n0+l];
  __syncthreads();

  int sub = tid/48, c4 = tid%48;
  float4 s3v = ((const float4*)g_s3)[c4];
  float4 c0v = ((const float4*)g_c0)[c4];
  const float4* TQ4  = (const float4*)g_TQ;
  const float4* Tit4 = (const float4*)g_Tit;
  const float4* Tut4 = (const float4*)g_Tut;
  const float4* Tnh4 = (const float4*)g_Tnh;
  const float4* Tna4 = (const float4*)g_Tna;

  for (int tl = sub; tl < 32; tl += 4) {
    int n = n0 + tl;
    float4 v  = TQ4 [(size_t)qi[tl]*48 + c4];
    float4 a  = Tit4[iti[tl]*48 + c4];
    float4 bu = Tut4[uti[tl]*48 + c4];
    float4 bh = Tnh4[nhi[tl]*48 + c4];
    float4 ba = Tna4[nai[tl]*48 + c4];
    float cr = cri[tl];
    float4 o;
    o.x = v.x + a.x + bu.x + bh.x + ba.x + cr*s3v.x + c0v.x;
    o.y = v.y + a.y + bu.y + bh.y + ba.y + cr*s3v.y + c0v.y;
    o.z = v.z + a.z + bu.z + bh.z + ba.z + cr*s3v.z + c0v.z;
    o.w = v.w + a.w + bu.w + bh.w + ba.w + cr*s3v.w + c0v.w;
    ((float4*)g_XP)[(size_t)n*48 + c4] = o;
  }
}

// ---- K4: GRU scan, thread-owns-gate (3 rows in regs), 1 barrier/step -------
__global__ void __launch_bounds__(64, 4) gru_kernel(const float* __restrict__ W_hh,
                                                    const float* __restrict__ b_hh)
{
  __shared__ __align__(16) float h_s[2][64];
  __shared__ float xp_s[4][192];        // ring
  int e = threadIdx.x;                  // 0..63, owns gate element e
  int b = blockIdx.x;

  ull wr[32], wz[32], wn[32];           // rows e, 64+e, 128+e
  {
    const ull* pr = (const ull*)(W_hh + (size_t)e*64);
    const ull* pz = (const ull*)(W_hh + (size_t)(64+e)*64);
    const ull* pn = (const ull*)(W_hh + (size_t)(128+e)*64);
    #pragma unroll
    for (int i = 0; i < 32; i++) { wr[i]=pr[i]; wz[i]=pz[i]; wn[i]=pn[i]; }
  }
  float br = b_hh[e], bz = b_hh[64+e], bn = b_hh[128+e];
  h_s[0][e] = 0.f;
  float hprev = 0.f;
  const float* xp = g_XP + (size_t)b*TT*192;
  float* hs = g_HS + (size_t)b*TT*64;
  unsigned sm0 = (unsigned)__cvta_generic_to_shared(&xp_s[0][0]);

  // prologue: groups for t = 0,1,2
  #pragma unroll
  for (int k = 0; k < 3; k++) {
    cpasync4(sm0 + (unsigned)(k*192 + e)*4u,       xp + (size_t)k*192 + e);
    cpasync4(sm0 + (unsigned)(k*192 + 64 + e)*4u,  xp + (size_t)k*192 + 64 + e);
    cpasync4(sm0 + (unsigned)(k*192 + 128 + e)*4u, xp + (size_t)k*192 + 128 + e);
    asm volatile("cp.async.commit_group;" ::: "memory");
  }
  __syncthreads();

  for (int t = 0; t < TT; t++) {
    asm volatile("cp.async.wait_group 2;" ::: "memory");   // group t landed
    {
      int tf = (t+3 < TT) ? t+3 : TT-1;
      int sl = (t+3) & 3;
      cpasync4(sm0 + (unsigned)(sl*192 + e)*4u,       xp + (size_t)tf*192 + e);
      cpasync4(sm0 + (unsigned)(sl*192 + 64 + e)*4u,  xp + (size_t)tf*192 + 64 + e);
      cpasync4(sm0 + (unsigned)(sl*192 + 128 + e)*4u, xp + (size_t)tf*192 + 128 + e);
      asm volatile("cp.async.commit_group;" ::: "memory");
    }

    ull ar0=0ull,ar1=0ull,az0=0ull,az1=0ull,an0=0ull,an1=0ull;
    const ulonglong2* h4 = (const ulonglong2*)h_s[t & 1];
    #pragma unroll
    for (int i = 0; i < 16; i++) {
      ulonglong2 p = h4[i];
      ar0 = ffma2(wr[2*i],   p.x, ar0);
      ar1 = ffma2(wr[2*i+1], p.y, ar1);
      az0 = ffma2(wz[2*i],   p.x, az0);
      az1 = ffma2(wz[2*i+1], p.y, az1);
      an0 = ffma2(wn[2*i],   p.x, an0);
      an1 = ffma2(wn[2*i+1], p.y, an1);
    }
    float r0,r1,r2,r3, z0,z1,z2,z3, n0,n1,n2,n3;
    unpack2(ar0,r0,r1); unpack2(ar1,r2,r3);
    unpack2(az0,z0,z1); unpack2(az1,z2,z3);
    unpack2(an0,n0,n1); unpack2(an1,n2,n3);
    const float* xc = xp_s[t & 3];
    float rg = siga(xc[e]      + (br + ((r0+r1)+(r2+r3))));
    float zg = siga(xc[64+e]   + (bz + ((z0+z1)+(z2+z3))));
    float ng = tanha(fmaf(rg, bn + ((n0+n1)+(n2+n3)), xc[128+e]));
    float hnew = fmaf(zg, hprev - ng, ng);
    h_s[(t+1)&1][e] = hnew;               // write to the OTHER buffer: no read conflict
    hprev = hnew;
    hs[(size_t)t*64 + e] = hnew;
    __syncthreads();                      // single barrier: publish h for step t+1
  }
}

// ---------------- K5+K6 fused: HL + readout (256 thr, 3 blocks/SM) ----------
__global__ void __launch_bounds__(256, 3) fout_kernel(
                            const float* __restrict__ la_W1, const float* __restrict__ la_b1,
                            const float* __restrict__ la_W2, const float* __restrict__ la_b2,
                            const int* __restrict__ qseq, float* __restrict__ out)
{
  extern __shared__ __align__(16) char sm_[];
  float* Ws = (float*)sm_;                 // [k*132 + row], 64*132 floats
  float* bs = Ws + 64*132;                 // 132 floats (+2 pad)
  ull*   tp = (ull*)(bs + 134);            // [pair*66 + k], 32 pairs
  __shared__ int qv_s[64];

  int tid = threadIdx.x, lane = tid & 31, wid = tid >> 5;
  int n0 = blockIdx.x * 64;

  if (tid < 64) {
    int idx = n0 + tid + 1; if (idx >= NTOK) idx = NTOK-1;
    qv_s[tid] = qseq[idx];
  }
  for (int i = tid; i < 132*64; i += 256) {
    int row = i >> 6, k = i & 63;
    Ws[k*132 + row] = la_W1[i];
  }
  if (tid < 132) bs[tid] = la_b1[tid];
  for (int i = tid; i < 64*16; i += 256) {
    int tok = i >> 4, c = i & 15;
    float4 v = ((const float4*)(g_HS + (size_t)(n0+tok)*64))[c];
    int p = tok >> 1, e = tok & 1;
    float* base = (float*)&tp[p*66 + 4*c];
    base[0+e] = v.x; base[2+e] = v.y; base[4+e] = v.z; base[6+e] = v.w;
  }
  __syncthreads();

  float b0 = bs[lane], b1v = bs[32+lane], b2v = bs[64+lane], b3v = bs[96+lane];
  float b4v = (lane < 4) ? bs[128+lane] : 0.f;
  ull acc[4][5];
  {
    ull p0=pack2(b0,b0), p1=pack2(b1v,b1v), p2=pack2(b2v,b2v), p3=pack2(b3v,b3v), p4=pack2(b4v,b4v);
    #pragma unroll
    for (int p = 0; p < 4; p++) { acc[p][0]=p0; acc[p][1]=p1; acc[p][2]=p2; acc[p][3]=p3; acc[p][4]=p4; }
  }
  int pbase = wid*4;
  #pragma unroll 4
  for (int k = 0; k < 64; k++) {
    float w0 = Ws[k*132 + lane];
    float w1 = Ws[k*132 + 32 + lane];
    float w2v = Ws[k*132 + 64 + lane];
    float w3 = Ws[k*132 + 96 + lane];
    float w4 = (lane < 4) ? Ws[k*132 + 128 + lane] : 0.f;
    ull d0=pack2(w0,w0), d1=pack2(w1,w1), d2=pack2(w2v,w2v), d3=pack2(w3,w3), d4=pack2(w4,w4);
    #pragma unroll
    for (int p = 0; p < 4; p++) {
      ull hd = tp[(pbase+p)*66 + k];
      acc[p][0] = ffma2(d0, hd, acc[p][0]);
      acc[p][1] = ffma2(d1, hd, acc[p][1]);
      acc[p][2] = ffma2(d2, hd, acc[p][2]);
      acc[p][3] = ffma2(d3, hd, acc[p][3]);
      acc[p][4] = ffma2(d4, hd, acc[p][4]);
    }
  }

  #pragma unroll
  for (int p = 0; p < 4; p++) {
    float va[5], vb[5];
    #pragma unroll
    for (int c = 0; c < 5; c++) {
      unpack2(acc[p][c], va[c], vb[c]);
      va[c] = fmaxf(va[c], 0.f);
      vb[c] = fmaxf(vb[c], 0.f);
    }
    #pragma unroll
    for (int e = 0; e < 2; e++) {
      int lt = (pbase + p)*2 + e;
      int n = n0 + lt;
      int bb = n / TT, it = n - bb*TT;
      if (it == TT-1) continue;
      float v0 = e ? vb[0] : va[0];
      float v1 = e ? vb[1] : va[1];
      float v2 = e ? vb[2] : va[2];
      float v3 = e ? vb[3] : va[3];
      float v4 = e ? vb[4] : va[4];

      int q = qv_s[lt];
      int4 c4 = g_qcls[q];
      int carr[4] = {c4.x, c4.y, c4.z, c4.w};
      float acc4[4];
      #pragma unroll
      for (int jj = 0; jj < 4; jj++) {
        int cc = (carr[jj] < 0) ? 0 : carr[jj];       // dummy row keeps loads uniform
        const float* w2r = la_W2 + (size_t)cc*MIDQ;
        float a = v0*w2r[lane] + v1*w2r[32+lane] + v2*w2r[64+lane] + v3*w2r[96+lane];
        if (lane < 4) a += v4*w2r[128+lane];
        acc4[jj] = a;
      }
      #pragma unroll
      for (int o = 16; o > 0; o >>= 1) {              // ILP-4 interleaved butterflies
        #pragma unroll
        for (int jj = 0; jj < 4; jj++) acc4[jj] += __shfl_xor_sync(0xffffffffu, acc4[jj], o);
      }
      if (lane == 0) {
        float S = 0.f;
        #pragma unroll
        for (int jj = 0; jj < 4; jj++)
          if (carr[jj] >= 0) S += fsig(acc4[jj] + la_b2[carr[jj]]);
        float sq = g_qSqd[q];
        float y = g_qdisc[q]*__fdividef(S - sq, sq + 1e-6f);
        out[bb*(TT-1) + it] = fsig(y);
      }
    }
  }
}

// ---------------- launcher --------------------------------------------------
extern "C" void kernel_launch(void* const* d_in, const int* in_sizes, int n_in,
                              void* d_out, int out_size)
{
  const float* E_q    = (const float*)d_in[0];
  const float* E_c    = (const float*)d_in[1];
  const float* E_it   = (const float*)d_in[2];
  const float* E_ut   = (const float*)d_in[3];
  const float* E_nh   = (const float*)d_in[4];
  const float* W_fuse = (const float*)d_in[5];
  const float* b_fuse = (const float*)d_in[6];
  const float* W_ih   = (const float*)d_in[7];
  const float* b_ih   = (const float*)d_in[8];
  const float* W_hh   = (const float*)d_in[9];
  const float* b_hh   = (const float*)d_in[10];
  const float* qd_W1  = (const float*)d_in[11];
  const float* qd_b1  = (const float*)d_in[12];
  const float* qd_W2  = (const float*)d_in[13];
  const float* qd_b2  = (const float*)d_in[14];
  const float* la_W1  = (const float*)d_in[15];
  const float* la_b1  = (const float*)d_in[16];
  const float* la_W2  = (const float*)d_in[17];
  const float* la_b2  = (const float*)d_in[18];
  const float* dc_W1  = (const float*)d_in[19];
  const float* dc_b1  = (const float*)d_in[20];
  const float* dc_W2  = (const float*)d_in[21];
  const float* dc_b2  = (const float*)d_in[22];

  int off = (in_sizes[23] > 1000000) ? 1 : 0;
  const int* qseq  = (const int*)d_in[23+off];
  const int* cseq  = (const int*)d_in[24+off];
  const int* itseq = (const int*)d_in[25+off];
  const int* utseq = (const int*)d_in[26+off];
  const int* nhseq = (const int*)d_in[27+off];
  const int* naseq = (const int*)d_in[28+off];
  const int* q2c   = (const int*)d_in[29+off];
  const int* q2cm  = (const int*)d_in[30+off];

  const int P0_SMEM = 33024;                          // max(tq 33024, hq 32768)
  const int FOUT_SMEM = (64*132 + 134)*4 + 32*66*8;   // 51224 bytes
  cudaFuncSetAttribute(fout_kernel, cudaFuncAttributeMaxDynamicSharedMemorySize, FOUT_SMEM);

  p0_kernel<<<842, 256, P0_SMEM>>>(E_q, E_c, E_it, E_ut, E_nh,
                                   W_ih, b_ih, W_fuse, b_fuse, qd_W1, qd_b1);
  p1b_kernel<<<(NQ+7)/8, 256>>>(E_q, qd_W2, qd_b2, dc_W1, dc_b1, dc_W2, dc_b2, q2c, q2cm);
  xp_kernel<<<NTOK/32, 192>>>(qseq, cseq, itseq, utseq, nhseq, naseq);
  gru_kernel<<<BB, 64>>>(W_hh, b_hh);            // launch #4 -> profiled
  fout_kernel<<<NTOK/64, 256, FOUT_SMEM>>>(la_W1, la_b1, la_W2, la_b2, qseq, (float*)d_out);
}

// round 16
// speedup vs baseline: 1.2277x; 1.0140x over previous
#include <cuda_runtime.h>
#include <math.h>

#define BB 512
#define TT 200
#define NTOK (BB*TT)          // 102400
#define MIDQ 132
#define NOUTS (BB*(TT-1))     // 101888
#define NQ 10001

// ---------------- scratch (device globals; no allocation) ----------------
__device__ float g_TQ [NQ*192];
__device__ float g_HQ [NQ*MIDQ];
__device__ float g_Tc [201*192];
__device__ float g_Tit[101*192];
__device__ float g_Tut[101*192];
__device__ float g_Tnh[101*192];
__device__ float g_Tna[101*192];
__device__ float g_c0[192], g_s3[192];
__device__ float g_XP[NTOK*192];
__device__ float g_HS[NTOK*64];
__device__ float g_qdisc[NQ], g_qSqd[NQ];
__device__ int4  g_qcls[NQ];

typedef unsigned long long ull;

__device__ __forceinline__ float fsig(float x){ return __fdividef(1.f, 1.f + __expf(-x)); }
__device__ __forceinline__ float tanha(float x){ float y; asm("tanh.approx.f32 %0,%1;" : "=f"(y) : "f"(x)); return y; }
__device__ __forceinline__ float siga(float x){ return fmaf(0.5f, tanha(0.5f*x), 0.5f); }

__device__ __forceinline__ ull pack2(float lo, float hi){
  ull r; asm("mov.b64 %0, {%1,%2};" : "=l"(r) : "f"(lo), "f"(hi)); return r;
}
__device__ __forceinline__ void unpack2(ull v, float& lo, float& hi){
  asm("mov.b64 {%0,%1}, %2;" : "=f"(lo), "=f"(hi) : "l"(v));
}
__device__ __forceinline__ ull ffma2(ull a, ull b, ull c){
  ull d; asm("fma.rn.f32x2 %0, %1, %2, %3;" : "=l"(d) : "l"(a), "l"(b), "l"(c)); return d;
}
__device__ __forceinline__ void cpasync4(unsigned smem, const void* g){
  asm volatile("cp.async.ca.shared.global [%0], [%1], 4;" :: "r"(smem), "l"(g));
}

// ================= P0: fused tables + tq_gemm + hq ==========================
// blocks [0,606): tables; [606,763): TQ gemm; [763,842): HQ
__global__ void p0_kernel(const float* __restrict__ E_q, const float* __restrict__ E_c,
                          const float* __restrict__ E_it, const float* __restrict__ E_ut,
                          const float* __restrict__ E_nh,
                          const float* __restrict__ W_ih, const float* __restrict__ b_ih,
                          const float* __restrict__ W_fuse, const float* __restrict__ b_fuse,
                          const float* __restrict__ qd_W1, const float* __restrict__ qd_b1)
{
  extern __shared__ __align__(16) char ps[];
  int tid = threadIdx.x;
  int blk = blockIdx.x;

  if (blk < 606) {
    float* e_s  = (float*)ps;
    float* tmp_s = e_s + 64;
    int b = blk, g = tid;
    if (b < 201) {
      if (g < 64) e_s[g] = E_c[b*64+g];
      __syncthreads();
      if (g < 192) {
        float acc = 0.f;
        #pragma unroll 8
        for (int k = 0; k < 64; k++) acc = fmaf(W_ih[g*320+64+k], e_s[k], acc);
        g_Tc[b*192+g] = acc;
      }
    } else if (b < 302) {
      int u = b - 201;
      if (g < 64) e_s[g] = E_it[u*64+g];
      __syncthreads();
      if (g < 192) {
        float acc = 0.f;
        #pragma unroll 8
        for (int k = 0; k < 64; k++) acc = fmaf(W_ih[g*320+192+k], e_s[k], acc);
        g_Tit[u*192+g] = acc;
      }
    } else if (b < 605) {
      int which = (b-302)/101, u = (b-302)%101;
      const float* E = (which == 0) ? E_ut : E_nh;
      int off = which*64;
      if (g < 64) e_s[g] = E[u*64+g];
      __syncthreads();
      if (g < 64) {
        float acc = 0.f;
        #pragma unroll 8
        for (int k = 0; k < 64; k++) acc = fmaf(W_fuse[g*192+off+k], e_s[k], acc);
        tmp_s[g] = acc;
      }
      __syncthreads();
      if (g < 192) {
        float acc = 0.f;
        #pragma unroll 8
        for (int d = 0; d < 64; d++) acc = fmaf(W_ih[g*320+256+d], tmp_s[d], acc);
        float* dst = (which == 0) ? g_Tut : (which == 1) ? g_Tnh : g_Tna;
        dst[u*192+g] = acc;
      }
    } else {
      if (g < 192) {
        float acc = b_ih[g], s = 0.f;
        #pragma unroll 8
        for (int d = 0; d < 64; d++) {
          acc = fmaf(W_ih[g*320+256+d], b_fuse[d], acc);
          s += W_ih[g*320+128+d];
        }
        g_c0[g] = acc; g_s3[g] = s;
      }
    }
  } else if (blk < 763) {
    float* Xs  = (float*)ps;        // 32*65
    float* Wsm = Xs + 32*65;        // 32*193
    int tx = tid & 15, ty = tid >> 4;
    int m0 = (blk - 606) * 64;
    float acc[4][12];
    #pragma unroll
    for (int p = 0; p < 4; p++)
      #pragma unroll
      for (int u = 0; u < 12; u++) acc[p][u] = 0.f;

    for (int kb = 0; kb < 64; kb += 32) {
      for (int i = tid; i < 64*32; i += 256) {
        int m = i >> 5, kk = i & 31;
        int row = m0 + m;
        Xs[kk*65+m] = (row < NQ) ? E_q[row*64 + kb + kk] : 0.f;
      }
      for (int i = tid; i < 192*32; i += 256) {
        int nn = i >> 5, kk = i & 31;
        Wsm[kk*193+nn] = W_ih[nn*320 + kb + kk];
      }
      __syncthreads();
      #pragma unroll
      for (int kk = 0; kk < 32; kk++) {
        float a[4], bb[12];
        #pragma unroll
        for (int p = 0; p < 4; p++) a[p] = Xs[kk*65 + ty*4 + p];
        #pragma unroll
        for (int u = 0; u < 12; u++) bb[u] = Wsm[kk*193 + tx*12 + u];
        #pragma unroll
        for (int p = 0; p < 4; p++)
          #pragma unroll
          for (int u = 0; u < 12; u++) acc[p][u] = fmaf(a[p], bb[u], acc[p][u]);
      }
      __syncthreads();
    }
    #pragma unroll
    for (int p = 0; p < 4; p++) {
      int m = m0 + ty*4 + p;
      if (m < NQ) {
        #pragma unroll
        for (int u = 0; u < 12; u++) g_TQ[(size_t)m*192 + tx*12 + u] = acc[p][u];
      }
    }
  } else {
    float* tile = (float*)ps;       // 128*64
    ull w2[32]; float bv = 0.f;
    if (tid < MIDQ) {
      const ull* wr = (const ull*)(qd_W1 + tid*64);
      #pragma unroll
      for (int k = 0; k < 32; k++) w2[k] = wr[k];
      bv = qd_b1[tid];
    }
    int tok0 = (blk - 763) * 128;
    for (int i = tid; i < 128*16; i += 256) {
      int r = i >> 4, c = i & 15;
      int row = tok0 + r; if (row >= NQ) row = NQ-1;
      ((float4*)tile)[r*16 + c] = ((const float4*)(E_q + (size_t)row*64))[c];
    }
    __syncthreads();
    if (tid < MIDQ) {
      for (int r = 0; r < 128; r += 2) {
        if (tok0 + r >= NQ) break;
        const ulonglong2* ha = (const ulonglong2*)(tile + r*64);
        const ulonglong2* hb = (const ulonglong2*)(tile + (r+1)*64);
        ull a0=0ull,a1=0ull,b0=0ull,b1=0ull;
        #pragma unroll
        for (int i2 = 0; i2 < 16; i2++) {
          ulonglong2 pa = ha[i2], pb = hb[i2];
          a0 = ffma2(w2[2*i2],   pa.x, a0);
          a1 = ffma2(w2[2*i2+1], pa.y, a1);
          b0 = ffma2(w2[2*i2],   pb.x, b0);
          b1 = ffma2(w2[2*i2+1], pb.y, b1);
        }
        float p0,p1,p2,p3,q0,q1,q2,q3;
        unpack2(a0,p0,p1); unpack2(a1,p2,p3);
        unpack2(b0,q0,q1); unpack2(b1,q2,q3);
        g_HQ[(size_t)(tok0+r)*MIDQ + tid] = fmaxf(bv + (p0+p1)+(p2+p3), 0.f);
        if (tok0+r+1 < NQ)
          g_HQ[(size_t)(tok0+r+1)*MIDQ + tid] = fmaxf(bv + (q0+q1)+(q2+q3), 0.f);
      }
    }
  }
}

// ---------------- P1b: warp-per-question heads + TQ fold --------------------
__global__ void p1b_kernel(const float* __restrict__ E_q,
                           const float* __restrict__ qd_W2, const float* __restrict__ qd_b2,
                           const float* __restrict__ dc_W1, const float* __restrict__ dc_b1,
                           const float* __restrict__ dc_W2, const float* __restrict__ dc_b2,
                           const int* __restrict__ q2c, const int* __restrict__ q2cm)
{
  __shared__ float dc1s[64*33];
  int tid = threadIdx.x;
  for (int i = tid; i < 32*64; i += 256) { int l = i >> 6, k = i & 63; dc1s[k*33+l] = dc_W1[i]; }
  __syncthreads();
  int lane = tid & 31, wid = tid >> 5;
  int q = blockIdx.x*8 + wid;
  if (q >= NQ) return;

  float h0 = g_HQ[(size_t)q*MIDQ + lane];
  float h1 = g_HQ[(size_t)q*MIDQ + lane + 32];
  float h2 = g_HQ[(size_t)q*MIDQ + lane + 64];
  float h3 = g_HQ[(size_t)q*MIDQ + lane + 96];
  float h4 = (lane < 4) ? g_HQ[(size_t)q*MIDQ + lane + 128] : 0.f;

  int cR = 0, mR = 0;
  if (lane < 4) { cR = q2c[q*4+lane]; mR = q2cm[q*4+lane]; }
  int cls[4], msk[4];
  #pragma unroll
  for (int j = 0; j < 4; j++) { cls[j] = __shfl_sync(0xffffffffu, cR, j); msk[j] = __shfl_sync(0xffffffffu, mR, j); }

  float qd[4];
  #pragma unroll
  for (int j = 0; j < 4; j++) {
    const float* wr = qd_W2 + (size_t)cls[j]*MIDQ;
    float acc = h0*wr[lane] + h1*wr[lane+32] + h2*wr[lane+64] + h3*wr[lane+96];
    if (lane < 4) acc += h4*wr[lane+128];
    #pragma unroll
    for (int o = 16; o > 0; o >>= 1) acc += __shfl_xor_sync(0xffffffffu, acc, o);
    qd[j] = fsig(acc + qd_b2[cls[j]]);
  }

  float dacc = dc_b1[lane];
  #pragma unroll 8
  for (int k = 0; k < 64; k++) dacc = fmaf(dc1s[k*33+lane], E_q[q*64+k], dacc);
  float dv = dc_W2[lane]*fmaxf(dacc, 0.f);
  #pragma unroll
  for (int o = 16; o > 0; o >>= 1) dv += __shfl_xor_sync(0xffffffffu, dv, o);

  float w[4]; float srel = 1e-6f;
  #pragma unroll
  for (int j = 0; j < 4; j++) srel += qd[j]*(float)msk[j];
  #pragma unroll
  for (int j = 0; j < 4; j++) w[j] = qd[j]*(float)msk[j]/srel;
  float S = 0.f; int cl[4];
  #pragma unroll
  for (int j = 0; j < 4; j++) {
    int c = cls[j]; bool fl = (msk[j] != 0);
    for (int j2 = 0; j2 < j; j2++) if (msk[j2] != 0 && cls[j2] == c) fl = false;
    if (fl) { S += qd[j]; cl[j] = c; } else cl[j] = -1;
  }
  if (lane == 0) {
    g_qSqd[q] = S;
    g_qcls[q] = make_int4(cl[0], cl[1], cl[2], cl[3]);
    g_qdisc[q] = fsig(dv + dc_b2[0])*10.f;
  }

  #pragma unroll
  for (int g = 0; g < 6; g++) {
    int o = g*32 + lane;
    float v = g_TQ[(size_t)q*192 + o];
    #pragma unroll
    for (int j = 0; j < 4; j++) v = fmaf(w[j], g_Tc[cls[j]*192 + o], v);
    g_TQ[(size_t)q*192 + o] = v;
  }
}

// ---------------- P2: XP[n] = gather-sum of tables --------------------------
__global__ void xp_kernel(const int* __restrict__ qseq, const int* __restrict__ cseq,
                          const int* __restrict__ itseq, const int* __restrict__ utseq,
                          const int* __restrict__ nhseq, const int* __restrict__ naseq)
{
  __shared__ int qi[32], iti[32], uti[32], nhi[32], nai[32];
  __shared__ float cri[32];
  int tid = threadIdx.x;
  int n0 = blockIdx.x*32;
  int grp = tid >> 5, l = tid & 31;
  if (grp == 0) qi[l]  = qseq [n0+l];
  else if (grp == 1) cri[l] = (float)cseq[n0+l];
  else if (grp == 2) iti[l] = itseq[n0+l];
  else if (grp == 3) uti[l] = utseq[n0+l];
  else if (grp == 4) nhi[l] = nhseq[n0+l];
  else               nai[l] = naseq[n0+l];
  __syncthreads();

  int sub = tid/48, c4 = tid%48;
  float4 s3v = ((const float4*)g_s3)[c4];
  float4 c0v = ((const float4*)g_c0)[c4];
  const float4* TQ4  = (const float4*)g_TQ;
  const float4* Tit4 = (const float4*)g_Tit;
  const float4* Tut4 = (const float4*)g_Tut;
  const float4* Tnh4 = (const float4*)g_Tnh;
  const float4* Tna4 = (const float4*)g_Tna;

  for (int tl = sub; tl < 32; tl += 4) {
    int n = n0 + tl;
    float4 v  = TQ4 [(size_t)qi[tl]*48 + c4];
    float4 a  = Tit4[iti[tl]*48 + c4];
    float4 bu = Tut4[uti[tl]*48 + c4];
    float4 bh = Tnh4[nhi[tl]*48 + c4];
    float4 ba = Tna4[nai[tl]*48 + c4];
    float cr = cri[tl];
    float4 o;
    o.x = v.x + a.x + bu.x + bh.x + ba.x + cr*s3v.x + c0v.x;
    o.y = v.y + a.y + bu.y + bh.y + ba.y + cr*s3v.y + c0v.y;
    o.z = v.z + a.z + bu.z + bh.z + ba.z + cr*s3v.z + c0v.z;
    o.w = v.w + a.w + bu.w + bh.w + ba.w + cr*s3v.w + c0v.w;
    ((float4*)g_XP)[(size_t)n*48 + c4] = o;
  }
}

// ---- K4: GRU scan, thread-owns-gate (3 rows in regs), 1 barrier/step -------
__global__ void __launch_bounds__(64, 4) gru_kernel(const float* __restrict__ W_hh,
                                                    const float* __restrict__ b_hh)
{
  __shared__ __align__(16) float h_s[2][64];
  __shared__ float xp_s[4][192];        // ring
  int e = threadIdx.x;                  // 0..63, owns gate element e
  int b = blockIdx.x;

  ull wr[32], wz[32], wn[32];           // rows e, 64+e, 128+e
  {
    const ull* pr = (const ull*)(W_hh + (size_t)e*64);
    const ull* pz = (const ull*)(W_hh + (size_t)(64+e)*64);
    const ull* pn = (const ull*)(W_hh + (size_t)(128+e)*64);
    #pragma unroll
    for (int i = 0; i < 32; i++) { wr[i]=pr[i]; wz[i]=pz[i]; wn[i]=pn[i]; }
  }
  float br = b_hh[e], bz = b_hh[64+e], bn = b_hh[128+e];
  h_s[0][e] = 0.f;
  float hprev = 0.f;
  const float* xp = g_XP + (size_t)b*TT*192;
  float* hs = g_HS + (size_t)b*TT*64;
  unsigned sm0 = (unsigned)__cvta_generic_to_shared(&xp_s[0][0]);

  // prologue: groups for t = 0,1,2
  #pragma unroll
  for (int k = 0; k < 3; k++) {
    cpasync4(sm0 + (unsigned)(k*192 + e)*4u,       xp + (size_t)k*192 + e);
    cpasync4(sm0 + (unsigned)(k*192 + 64 + e)*4u,  xp + (size_t)k*192 + 64 + e);
    cpasync4(sm0 + (unsigned)(k*192 + 128 + e)*4u, xp + (size_t)k*192 + 128 + e);
    asm volatile("cp.async.commit_group;" ::: "memory");
  }
  __syncthreads();

  for (int t = 0; t < TT; t++) {
    asm volatile("cp.async.wait_group 2;" ::: "memory");   // group t landed
    {
      int tf = (t+3 < TT) ? t+3 : TT-1;
      int sl = (t+3) & 3;
      cpasync4(sm0 + (unsigned)(sl*192 + e)*4u,       xp + (size_t)tf*192 + e);
      cpasync4(sm0 + (unsigned)(sl*192 + 64 + e)*4u,  xp + (size_t)tf*192 + 64 + e);
      cpasync4(sm0 + (unsigned)(sl*192 + 128 + e)*4u, xp + (size_t)tf*192 + 128 + e);
      asm volatile("cp.async.commit_group;" ::: "memory");
    }

    ull ar0=0ull,ar1=0ull,az0=0ull,az1=0ull,an0=0ull,an1=0ull;
    const ulonglong2* h4 = (const ulonglong2*)h_s[t & 1];
    #pragma unroll
    for (int i = 0; i < 16; i++) {
      ulonglong2 p = h4[i];
      ar0 = ffma2(wr[2*i],   p.x, ar0);
      ar1 = ffma2(wr[2*i+1], p.y, ar1);
      az0 = ffma2(wz[2*i],   p.x, az0);
      az1 = ffma2(wz[2*i+1], p.y, az1);
      an0 = ffma2(wn[2*i],   p.x, an0);
      an1 = ffma2(wn[2*i+1], p.y, an1);
    }
    float r0,r1,r2,r3, z0,z1,z2,z3, n0,n1,n2,n3;
    unpack2(ar0,r0,r1); unpack2(ar1,r2,r3);
    unpack2(az0,z0,z1); unpack2(az1,z2,z3);
    unpack2(an0,n0,n1); unpack2(an1,n2,n3);
    const float* xc = xp_s[t & 3];
    float rg = siga(xc[e]      + (br + ((r0+r1)+(r2+r3))));
    float zg = siga(xc[64+e]   + (bz + ((z0+z1)+(z2+z3))));
    float ng = tanha(fmaf(rg, bn + ((n0+n1)+(n2+n3)), xc[128+e]));
    float hnew = fmaf(zg, hprev - ng, ng);
    h_s[(t+1)&1][e] = hnew;               // write to the OTHER buffer: no read conflict
    hprev = hnew;
    hs[(size_t)t*64 + e] = hnew;
    __syncthreads();                      // single barrier: publish h for step t+1
  }
}

// ---------------- K5+K6 fused: HL + readout (hoisted scalar lookups) --------
__global__ void __launch_bounds__(256, 3) fout_kernel(
                            const float* __restrict__ la_W1, const float* __restrict__ la_b1,
                            const float* __restrict__ la_W2, const float* __restrict__ la_b2,
                            const int* __restrict__ qseq, float* __restrict__ out)
{
  extern __shared__ __align__(16) char sm_[];
  float* Ws  = (float*)sm_;                // [k*132 + row], 64*132 floats
  float* bs  = Ws + 64*132;                // 134 floats (132 + pad)
  float* bs2 = bs + 134;                   // la_b2 staged, 200 floats
  ull*   tp  = (ull*)(bs2 + 200);          // [pair*66 + k], 32 pairs
  __shared__ int4  cls_s[64];
  __shared__ float sqd_s[64], dsc_s[64];

  int tid = threadIdx.x, lane = tid & 31, wid = tid >> 5;
  int n0 = blockIdx.x * 64;

  // hoisted per-token scalar chains (self-consistent per thread, no sync needed yet)
  if (tid < 64) {
    int idx = n0 + tid + 1; if (idx >= NTOK) idx = NTOK-1;
    int q = qseq[idx];
    cls_s[tid] = g_qcls[q];
    sqd_s[tid] = g_qSqd[q];
    dsc_s[tid] = g_qdisc[q];
  }
  for (int i = tid; i < 132*64; i += 256) {
    int row = i >> 6, k = i & 63;
    Ws[k*132 + row] = la_W1[i];
  }
  if (tid < 132) bs[tid] = la_b1[tid];
  for (int i = tid; i < 200; i += 256) bs2[i] = la_b2[i];
  for (int i = tid; i < 64*16; i += 256) {
    int tok = i >> 4, c = i & 15;
    float4 v = ((const float4*)(g_HS + (size_t)(n0+tok)*64))[c];
    int p = tok >> 1, e = tok & 1;
    float* base = (float*)&tp[p*66 + 4*c];
    base[0+e] = v.x; base[2+e] = v.y; base[4+e] = v.z; base[6+e] = v.w;
  }
  __syncthreads();

  float b0 = bs[lane], b1v = bs[32+lane], b2v = bs[64+lane], b3v = bs[96+lane];
  float b4v = (lane < 4) ? bs[128+lane] : 0.f;
  ull acc[4][5];
  {
    ull p0=pack2(b0,b0), p1=pack2(b1v,b1v), p2=pack2(b2v,b2v), p3=pack2(b3v,b3v), p4=pack2(b4v,b4v);
    #pragma unroll
    for (int p = 0; p < 4; p++) { acc[p][0]=p0; acc[p][1]=p1; acc[p][2]=p2; acc[p][3]=p3; acc[p][4]=p4; }
  }
  int pbase = wid*4;
  #pragma unroll 4
  for (int k = 0; k < 64; k++) {
    float w0 = Ws[k*132 + lane];
    float w1 = Ws[k*132 + 32 + lane];
    float w2v = Ws[k*132 + 64 + lane];
    float w3 = Ws[k*132 + 96 + lane];
    float w4 = (lane < 4) ? Ws[k*132 + 128 + lane] : 0.f;
    ull d0=pack2(w0,w0), d1=pack2(w1,w1), d2=pack2(w2v,w2v), d3=pack2(w3,w3), d4=pack2(w4,w4);
    #pragma unroll
    for (int p = 0; p < 4; p++) {
      ull hd = tp[(pbase+p)*66 + k];
      acc[p][0] = ffma2(d0, hd, acc[p][0]);
      acc[p][1] = ffma2(d1, hd, acc[p][1]);
      acc[p][2] = ffma2(d2, hd, acc[p][2]);
      acc[p][3] = ffma2(d3, hd, acc[p][3]);
      acc[p][4] = ffma2(d4, hd, acc[p][4]);
    }
  }

  #pragma unroll
  for (int p = 0; p < 4; p++) {
    float va[5], vb[5];
    #pragma unroll
    for (int c = 0; c < 5; c++) {
      unpack2(acc[p][c], va[c], vb[c]);
      va[c] = fmaxf(va[c], 0.f);
      vb[c] = fmaxf(vb[c], 0.f);
    }
    #pragma unroll
    for (int e = 0; e < 2; e++) {
      int lt = (pbase + p)*2 + e;
      int n = n0 + lt;
      int bb = n / TT, it = n - bb*TT;
      if (it == TT-1) continue;
      float v0 = e ? vb[0] : va[0];
      float v1 = e ? vb[1] : va[1];
      float v2 = e ? vb[2] : va[2];
      float v3 = e ? vb[3] : va[3];
      float v4 = e ? vb[4] : va[4];

      int4 c4 = cls_s[lt];
      int carr[4] = {c4.x, c4.y, c4.z, c4.w};
      float acc4[4];
      #pragma unroll
      for (int jj = 0; jj < 4; jj++) {
        int cc = (carr[jj] < 0) ? 0 : carr[jj];       // dummy row keeps loads uniform
        const float* w2r = la_W2 + (size_t)cc*MIDQ;
        float a = v0*w2r[lane] + v1*w2r[32+lane] + v2*w2r[64+lane] + v3*w2r[96+lane];
        if (lane < 4) a += v4*w2r[128+lane];
        acc4[jj] = a;
      }
      #pragma unroll
      for (int o = 16; o > 0; o >>= 1) {              // ILP-4 interleaved butterflies
        #pragma unroll
        for (int jj = 0; jj < 4; jj++) acc4[jj] += __shfl_xor_sync(0xffffffffu, acc4[jj], o);
      }
      if (lane == 0) {
        float S = 0.f;
        #pragma unroll
        for (int jj = 0; jj < 4; jj++)
          if (carr[jj] >= 0) S += fsig(acc4[jj] + bs2[carr[jj]]);
        float sq = sqd_s[lt];
        float y = dsc_s[lt]*__fdividef(S - sq, sq + 1e-6f);
        out[bb*(TT-1) + it] = fsig(y);
      }
    }
  }
}

// ---------------- launcher --------------------------------------------------
extern "C" void kernel_launch(void* const* d_in, const int* in_sizes, int n_in,
                              void* d_out, int out_size)
{
  const float* E_q    = (const float*)d_in[0];
  const float* E_c    = (const float*)d_in[1];
  const float* E_it   = (const float*)d_in[2];
  const float* E_ut   = (const float*)d_in[3];
  const float* E_nh   = (const float*)d_in[4];
  const float* W_fuse = (const float*)d_in[5];
  const float* b_fuse = (const float*)d_in[6];
  const float* W_ih   = (const float*)d_in[7];
  const float* b_ih   = (const float*)d_in[8];
  const float* W_hh   = (const float*)d_in[9];
  const float* b_hh   = (const float*)d_in[10];
  const float* qd_W1  = (const float*)d_in[11];
  const float* qd_b1  = (const float*)d_in[12];
  const float* qd_W2  = (const float*)d_in[13];
  const float* qd_b2  = (const float*)d_in[14];
  const float* la_W1  = (const float*)d_in[15];
  const float* la_b1  = (const float*)d_in[16];
  const float* la_W2  = (const float*)d_in[17];
  const float* la_b2  = (const float*)d_in[18];
  const float* dc_W1  = (const float*)d_in[19];
  const float* dc_b1  = (const float*)d_in[20];
  const float* dc_W2  = (const float*)d_in[21];
  const float* dc_b2  = (const float*)d_in[22];

  int off = (in_sizes[23] > 1000000) ? 1 : 0;
  const int* qseq  = (const int*)d_in[23+off];
  const int* cseq  = (const int*)d_in[24+off];
  const int* itseq = (const int*)d_in[25+off];
  const int* utseq = (const int*)d_in[26+off];
  const int* nhseq = (const int*)d_in[27+off];
  const int* naseq = (const int*)d_in[28+off];
  const int* q2c   = (const int*)d_in[29+off];
  const int* q2cm  = (const int*)d_in[30+off];

  const int P0_SMEM = 33024;                                // max(tq 33024, hq 32768)
  const int FOUT_SMEM = (64*132 + 134 + 200)*4 + 32*66*8;   // 52024 bytes
  cudaFuncSetAttribute(fout_kernel, cudaFuncAttributeMaxDynamicSharedMemorySize, FOUT_SMEM);

  p0_kernel<<<842, 256, P0_SMEM>>>(E_q, E_c, E_it, E_ut, E_nh,
                                   W_ih, b_ih, W_fuse, b_fuse, qd_W1, qd_b1);
  p1b_kernel<<<(NQ+7)/8, 256>>>(E_q, qd_W2, qd_b2, dc_W1, dc_b1, dc_W2, dc_b2, q2c, q2cm);
  xp_kernel<<<NTOK/32, 192>>>(qseq, cseq, itseq, utseq, nhseq, naseq);
  gru_kernel<<<BB, 64>>>(W_hh, b_hh);            // launch #4 -> profiled
  fout_kernel<<<NTOK/64, 256, FOUT_SMEM>>>(la_W1, la_b1, la_W2, la_b2, qseq, (float*)d_out);
}

// round 17
// speedup vs baseline: 1.2427x; 1.0122x over previous
#include <cuda_runtime.h>
#include <math.h>

#define BB 512
#define TT 200
#define NTOK (BB*TT)          // 102400
#define MIDQ 132
#define NOUTS (BB*(TT-1))     // 101888
#define NQ 10001

// ---------------- scratch (device globals; no allocation) ----------------
__device__ float g_TQ [NQ*192];
__device__ float g_HQ [NQ*MIDQ];
__device__ float g_Tc [201*192];
__device__ float g_Tit[101*192];
__device__ float g_Tut[101*192];
__device__ float g_Tnh[101*192];
__device__ float g_Tna[101*192];
__device__ float g_c0[192], g_s3[192];
__device__ float g_XP[NTOK*192];
__device__ float g_HS[NTOK*64];
__device__ float g_qdisc[NQ], g_qSqd[NQ];
__device__ int4  g_qcls[NQ];

typedef unsigned long long ull;

__device__ __forceinline__ float fsig(float x){ return __fdividef(1.f, 1.f + __expf(-x)); }
__device__ __forceinline__ float tanha(float x){ float y; asm("tanh.approx.f32 %0,%1;" : "=f"(y) : "f"(x)); return y; }
__device__ __forceinline__ float siga(float x){ return fmaf(0.5f, tanha(0.5f*x), 0.5f); }

__device__ __forceinline__ ull pack2(float lo, float hi){
  ull r; asm("mov.b64 %0, {%1,%2};" : "=l"(r) : "f"(lo), "f"(hi)); return r;
}
__device__ __forceinline__ void unpack2(ull v, float& lo, float& hi){
  asm("mov.b64 {%0,%1}, %2;" : "=f"(lo), "=f"(hi) : "l"(v));
}
__device__ __forceinline__ ull ffma2(ull a, ull b, ull c){
  ull d; asm("fma.rn.f32x2 %0, %1, %2, %3;" : "=l"(d) : "l"(a), "l"(b), "l"(c)); return d;
}
__device__ __forceinline__ void cpasync4(unsigned smem, const void* g){
  asm volatile("cp.async.ca.shared.global [%0], [%1], 4;" :: "r"(smem), "l"(g));
}

// ================= P0: fused tables + tq_gemm + hq ==========================
// blocks [0,606): tables; [606,763): TQ gemm; [763,842): HQ
__global__ void p0_kernel(const float* __restrict__ E_q, const float* __restrict__ E_c,
                          const float* __restrict__ E_it, const float* __restrict__ E_ut,
                          const float* __restrict__ E_nh,
                          const float* __restrict__ W_ih, const float* __restrict__ b_ih,
                          const float* __restrict__ W_fuse, const float* __restrict__ b_fuse,
                          const float* __restrict__ qd_W1, const float* __restrict__ qd_b1)
{
  extern __shared__ __align__(16) char ps[];
  int tid = threadIdx.x;
  int blk = blockIdx.x;

  if (blk < 606) {
    float* e_s  = (float*)ps;
    float* tmp_s = e_s + 64;
    int b = blk, g = tid;
    if (b < 201) {
      if (g < 64) e_s[g] = E_c[b*64+g];
      __syncthreads();
      if (g < 192) {
        float acc = 0.f;
        #pragma unroll 8
        for (int k = 0; k < 64; k++) acc = fmaf(W_ih[g*320+64+k], e_s[k], acc);
        g_Tc[b*192+g] = acc;
      }
    } else if (b < 302) {
      int u = b - 201;
      if (g < 64) e_s[g] = E_it[u*64+g];
      __syncthreads();
      if (g < 192) {
        float acc = 0.f;
        #pragma unroll 8
        for (int k = 0; k < 64; k++) acc = fmaf(W_ih[g*320+192+k], e_s[k], acc);
        g_Tit[u*192+g] = acc;
      }
    } else if (b < 605) {
      int which = (b-302)/101, u = (b-302)%101;
      const float* E = (which == 0) ? E_ut : E_nh;
      int off = which*64;
      if (g < 64) e_s[g] = E[u*64+g];
      __syncthreads();
      if (g < 64) {
        float acc = 0.f;
        #pragma unroll 8
        for (int k = 0; k < 64; k++) acc = fmaf(W_fuse[g*192+off+k], e_s[k], acc);
        tmp_s[g] = acc;
      }
      __syncthreads();
      if (g < 192) {
        float acc = 0.f;
        #pragma unroll 8
        for (int d = 0; d < 64; d++) acc = fmaf(W_ih[g*320+256+d], tmp_s[d], acc);
        float* dst = (which == 0) ? g_Tut : (which == 1) ? g_Tnh : g_Tna;
        dst[u*192+g] = acc;
      }
    } else {
      if (g < 192) {
        float acc = b_ih[g], s = 0.f;
        #pragma unroll 8
        for (int d = 0; d < 64; d++) {
          acc = fmaf(W_ih[g*320+256+d], b_fuse[d], acc);
          s += W_ih[g*320+128+d];
        }
        g_c0[g] = acc; g_s3[g] = s;
      }
    }
  } else if (blk < 763) {
    float* Xs  = (float*)ps;        // 32*65
    float* Wsm = Xs + 32*65;        // 32*193
    int tx = tid & 15, ty = tid >> 4;
    int m0 = (blk - 606) * 64;
    float acc[4][12];
    #pragma unroll
    for (int p = 0; p < 4; p++)
      #pragma unroll
      for (int u = 0; u < 12; u++) acc[p][u] = 0.f;

    for (int kb = 0; kb < 64; kb += 32) {
      for (int i = tid; i < 64*32; i += 256) {
        int m = i >> 5, kk = i & 31;
        int row = m0 + m;
        Xs[kk*65+m] = (row < NQ) ? E_q[row*64 + kb + kk] : 0.f;
      }
      for (int i = tid; i < 192*32; i += 256) {
        int nn = i >> 5, kk = i & 31;
        Wsm[kk*193+nn] = W_ih[nn*320 + kb + kk];
      }
      __syncthreads();
      #pragma unroll
      for (int kk = 0; kk < 32; kk++) {
        float a[4], bb[12];
        #pragma unroll
        for (int p = 0; p < 4; p++) a[p] = Xs[kk*65 + ty*4 + p];
        #pragma unroll
        for (int u = 0; u < 12; u++) bb[u] = Wsm[kk*193 + tx*12 + u];
        #pragma unroll
        for (int p = 0; p < 4; p++)
          #pragma unroll
          for (int u = 0; u < 12; u++) acc[p][u] = fmaf(a[p], bb[u], acc[p][u]);
      }
      __syncthreads();
    }
    #pragma unroll
    for (int p = 0; p < 4; p++) {
      int m = m0 + ty*4 + p;
      if (m < NQ) {
        #pragma unroll
        for (int u = 0; u < 12; u++) g_TQ[(size_t)m*192 + tx*12 + u] = acc[p][u];
      }
    }
  } else {
    float* tile = (float*)ps;       // 128*64
    ull w2[32]; float bv = 0.f;
    if (tid < MIDQ) {
      const ull* wr = (const ull*)(qd_W1 + tid*64);
      #pragma unroll
      for (int k = 0; k < 32; k++) w2[k] = wr[k];
      bv = qd_b1[tid];
    }
    int tok0 = (blk - 763) * 128;
    for (int i = tid; i < 128*16; i += 256) {
      int r = i >> 4, c = i & 15;
      int row = tok0 + r; if (row >= NQ) row = NQ-1;
      ((float4*)tile)[r*16 + c] = ((const float4*)(E_q + (size_t)row*64))[c];
    }
    __syncthreads();
    if (tid < MIDQ) {
      for (int r = 0; r < 128; r += 2) {
        if (tok0 + r >= NQ) break;
        const ulonglong2* ha = (const ulonglong2*)(tile + r*64);
        const ulonglong2* hb = (const ulonglong2*)(tile + (r+1)*64);
        ull a0=0ull,a1=0ull,b0=0ull,b1=0ull;
        #pragma unroll
        for (int i2 = 0; i2 < 16; i2++) {
          ulonglong2 pa = ha[i2], pb = hb[i2];
          a0 = ffma2(w2[2*i2],   pa.x, a0);
          a1 = ffma2(w2[2*i2+1], pa.y, a1);
          b0 = ffma2(w2[2*i2],   pb.x, b0);
          b1 = ffma2(w2[2*i2+1], pb.y, b1);
        }
        float p0,p1,p2,p3,q0,q1,q2,q3;
        unpack2(a0,p0,p1); unpack2(a1,p2,p3);
        unpack2(b0,q0,q1); unpack2(b1,q2,q3);
        g_HQ[(size_t)(tok0+r)*MIDQ + tid] = fmaxf(bv + (p0+p1)+(p2+p3), 0.f);
        if (tok0+r+1 < NQ)
          g_HQ[(size_t)(tok0+r+1)*MIDQ + tid] = fmaxf(bv + (q0+q1)+(q2+q3), 0.f);
      }
    }
  }
}

// ---------------- P1b: warp-per-question heads + TQ fold --------------------
__global__ void p1b_kernel(const float* __restrict__ E_q,
                           const float* __restrict__ qd_W2, const float* __restrict__ qd_b2,
                           const float* __restrict__ dc_W1, const float* __restrict__ dc_b1,
                           const float* __restrict__ dc_W2, const float* __restrict__ dc_b2,
                           const int* __restrict__ q2c, const int* __restrict__ q2cm)
{
  __shared__ float dc1s[64*33];
  int tid = threadIdx.x;
  for (int i = tid; i < 32*64; i += 256) { int l = i >> 6, k = i & 63; dc1s[k*33+l] = dc_W1[i]; }
  __syncthreads();
  int lane = tid & 31, wid = tid >> 5;
  int q = blockIdx.x*8 + wid;
  if (q >= NQ) return;

  float h0 = g_HQ[(size_t)q*MIDQ + lane];
  float h1 = g_HQ[(size_t)q*MIDQ + lane + 32];
  float h2 = g_HQ[(size_t)q*MIDQ + lane + 64];
  float h3 = g_HQ[(size_t)q*MIDQ + lane + 96];
  float h4 = (lane < 4) ? g_HQ[(size_t)q*MIDQ + lane + 128] : 0.f;

  int cR = 0, mR = 0;
  if (lane < 4) { cR = q2c[q*4+lane]; mR = q2cm[q*4+lane]; }
  int cls[4], msk[4];
  #pragma unroll
  for (int j = 0; j < 4; j++) { cls[j] = __shfl_sync(0xffffffffu, cR, j); msk[j] = __shfl_sync(0xffffffffu, mR, j); }

  float qd[4];
  #pragma unroll
  for (int j = 0; j < 4; j++) {
    const float* wr = qd_W2 + (size_t)cls[j]*MIDQ;
    float acc = h0*wr[lane] + h1*wr[lane+32] + h2*wr[lane+64] + h3*wr[lane+96];
    if (lane < 4) acc += h4*wr[lane+128];
    #pragma unroll
    for (int o = 16; o > 0; o >>= 1) acc += __shfl_xor_sync(0xffffffffu, acc, o);
    qd[j] = fsig(acc + qd_b2[cls[j]]);
  }

  float dacc = dc_b1[lane];
  #pragma unroll 8
  for (int k = 0; k < 64; k++) dacc = fmaf(dc1s[k*33+lane], E_q[q*64+k], dacc);
  float dv = dc_W2[lane]*fmaxf(dacc, 0.f);
  #pragma unroll
  for (int o = 16; o > 0; o >>= 1) dv += __shfl_xor_sync(0xffffffffu, dv, o);

  float w[4]; float srel = 1e-6f;
  #pragma unroll
  for (int j = 0; j < 4; j++) srel += qd[j]*(float)msk[j];
  #pragma unroll
  for (int j = 0; j < 4; j++) w[j] = qd[j]*(float)msk[j]/srel;
  float S = 0.f; int cl[4];
  #pragma unroll
  for (int j = 0; j < 4; j++) {
    int c = cls[j]; bool fl = (msk[j] != 0);
    for (int j2 = 0; j2 < j; j2++) if (msk[j2] != 0 && cls[j2] == c) fl = false;
    if (fl) { S += qd[j]; cl[j] = c; } else cl[j] = -1;
  }
  if (lane == 0) {
    g_qSqd[q] = S;
    g_qcls[q] = make_int4(cl[0], cl[1], cl[2], cl[3]);
    g_qdisc[q] = fsig(dv + dc_b2[0])*10.f;
  }

  #pragma unroll
  for (int g = 0; g < 6; g++) {
    int o = g*32 + lane;
    float v = g_TQ[(size_t)q*192 + o];
    #pragma unroll
    for (int j = 0; j < 4; j++) v = fmaf(w[j], g_Tc[cls[j]*192 + o], v);
    g_TQ[(size_t)q*192 + o] = v;
  }
}

// ---------------- P2: XP[n] = gather-sum of tables --------------------------
__global__ void xp_kernel(const int* __restrict__ qseq, const int* __restrict__ cseq,
                          const int* __restrict__ itseq, const int* __restrict__ utseq,
                          const int* __restrict__ nhseq, const int* __restrict__ naseq)
{
  __shared__ int qi[32], iti[32], uti[32], nhi[32], nai[32];
  __shared__ float cri[32];
  int tid = threadIdx.x;
  int n0 = blockIdx.x*32;
  int grp = tid >> 5, l = tid & 31;
  if (grp == 0) qi[l]  = qseq [n0+l];
  else if (grp == 1) cri[l] = (float)cseq[n0+l];
  else if (grp == 2) iti[l] = itseq[n0+l];
  else if (grp == 3) uti[l] = utseq[n0+l];
  else if (grp == 4) nhi[l] = nhseq[n0+l];
  else               nai[l] = naseq[n0+l];
  __syncthreads();

  int sub = tid/48, c4 = tid%48;
  float4 s3v = ((const float4*)g_s3)[c4];
  float4 c0v = ((const float4*)g_c0)[c4];
  const float4* TQ4  = (const float4*)g_TQ;
  const float4* Tit4 = (const float4*)g_Tit;
  const float4* Tut4 = (const float4*)g_Tut;
  const float4* Tnh4 = (const float4*)g_Tnh;
  const float4* Tna4 = (const float4*)g_Tna;

  for (int tl = sub; tl < 32; tl += 4) {
    int n = n0 + tl;
    float4 v  = TQ4 [(size_t)qi[tl]*48 + c4];
    float4 a  = Tit4[iti[tl]*48 + c4];
    float4 bu = Tut4[uti[tl]*48 + c4];
    float4 bh = Tnh4[nhi[tl]*48 + c4];
    float4 ba = Tna4[nai[tl]*48 + c4];
    float cr = cri[tl];
    float4 o;
    o.x = v.x + a.x + bu.x + bh.x + ba.x + cr*s3v.x + c0v.x;
    o.y = v.y + a.y + bu.y + bh.y + ba.y + cr*s3v.y + c0v.y;
    o.z = v.z + a.z + bu.z + bh.z + ba.z + cr*s3v.z + c0v.z;
    o.w = v.w + a.w + bu.w + bh.w + ba.w + cr*s3v.w + c0v.w;
    ((float4*)g_XP)[(size_t)n*48 + c4] = o;
  }
}

// ---- K4: GRU scan, thread-owns-gate (3 rows in regs), 1 barrier/step -------
__global__ void __launch_bounds__(64, 4) gru_kernel(const float* __restrict__ W_hh,
                                                    const float* __restrict__ b_hh)
{
  __shared__ __align__(16) float h_s[2][64];
  __shared__ float xp_s[4][192];        // ring
  int e = threadIdx.x;                  // 0..63, owns gate element e
  int b = blockIdx.x;

  ull wr[32], wz[32], wn[32];           // rows e, 64+e, 128+e
  {
    const ull* pr = (const ull*)(W_hh + (size_t)e*64);
    const ull* pz = (const ull*)(W_hh + (size_t)(64+e)*64);
    const ull* pn = (const ull*)(W_hh + (size_t)(128+e)*64);
    #pragma unroll
    for (int i = 0; i < 32; i++) { wr[i]=pr[i]; wz[i]=pz[i]; wn[i]=pn[i]; }
  }
  float br = b_hh[e], bz = b_hh[64+e], bn = b_hh[128+e];
  h_s[0][e] = 0.f;
  float hprev = 0.f;
  const float* xp = g_XP + (size_t)b*TT*192;
  float* hs = g_HS + (size_t)b*TT*64;
  unsigned sm0 = (unsigned)__cvta_generic_to_shared(&xp_s[0][0]);

  // prologue: groups for t = 0,1,2
  #pragma unroll
  for (int k = 0; k < 3; k++) {
    cpasync4(sm0 + (unsigned)(k*192 + e)*4u,       xp + (size_t)k*192 + e);
    cpasync4(sm0 + (unsigned)(k*192 + 64 + e)*4u,  xp + (size_t)k*192 + 64 + e);
    cpasync4(sm0 + (unsigned)(k*192 + 128 + e)*4u, xp + (size_t)k*192 + 128 + e);
    asm volatile("cp.async.commit_group;" ::: "memory");
  }
  __syncthreads();

  for (int t = 0; t < TT; t++) {
    asm volatile("cp.async.wait_group 2;" ::: "memory");   // group t landed
    {
      int tf = (t+3 < TT) ? t+3 : TT-1;
      int sl = (t+3) & 3;
      cpasync4(sm0 + (unsigned)(sl*192 + e)*4u,       xp + (size_t)tf*192 + e);
      cpasync4(sm0 + (unsigned)(sl*192 + 64 + e)*4u,  xp + (size_t)tf*192 + 64 + e);
      cpasync4(sm0 + (unsigned)(sl*192 + 128 + e)*4u, xp + (size_t)tf*192 + 128 + e);
      asm volatile("cp.async.commit_group;" ::: "memory");
    }

    ull ar0=0ull,ar1=0ull,az0=0ull,az1=0ull,an0=0ull,an1=0ull;
    const ulonglong2* h4 = (const ulonglong2*)h_s[t & 1];
    #pragma unroll
    for (int i = 0; i < 16; i++) {
      ulonglong2 p = h4[i];
      ar0 = ffma2(wr[2*i],   p.x, ar0);
      ar1 = ffma2(wr[2*i+1], p.y, ar1);
      az0 = ffma2(wz[2*i],   p.x, az0);
      az1 = ffma2(wz[2*i+1], p.y, az1);
      an0 = ffma2(wn[2*i],   p.x, an0);
      an1 = ffma2(wn[2*i+1], p.y, an1);
    }
    float r0,r1,r2,r3, z0,z1,z2,z3, n0,n1,n2,n3;
    unpack2(ar0,r0,r1); unpack2(ar1,r2,r3);
    unpack2(az0,z0,z1); unpack2(az1,z2,z3);
    unpack2(an0,n0,n1); unpack2(an1,n2,n3);
    const float* xc = xp_s[t & 3];
    float rg = siga(xc[e]      + (br + ((r0+r1)+(r2+r3))));
    float zg = siga(xc[64+e]   + (bz + ((z0+z1)+(z2+z3))));
    float ng = tanha(fmaf(rg, bn + ((n0+n1)+(n2+n3)), xc[128+e]));
    float hnew = fmaf(zg, hprev - ng, ng);
    h_s[(t+1)&1][e] = hnew;               // write to the OTHER buffer: no read conflict
    hprev = hnew;
    hs[(size_t)t*64 + e] = hnew;
    __syncthreads();                      // single barrier: publish h for step t+1
  }
}

// ---------------- K5+K6 fused: HL + readout (LDS.128 tp, ILP-8 epilogue) ----
__global__ void __launch_bounds__(256, 3) fout_kernel(
                            const float* __restrict__ la_W1, const float* __restrict__ la_b1,
                            const float* __restrict__ la_W2, const float* __restrict__ la_b2,
                            const int* __restrict__ qseq, float* __restrict__ out)
{
  extern __shared__ __align__(16) char sm_[];
  float* Ws  = (float*)sm_;                // [k*132 + row], 64*132 floats
  float* bs  = Ws + 64*132;                // 134
  float* bs2 = bs + 134;                   // 202 (la_b2 + pad for 16B align of tp)
  ull*   tp  = (ull*)(bs2 + 202);          // [pair*66 + k], 32 pairs; 16B-aligned
  __shared__ int4  cls_s[64];
  __shared__ float sqd_s[64], dsc_s[64];

  int tid = threadIdx.x, lane = tid & 31, wid = tid >> 5;
  int n0 = blockIdx.x * 64;

  if (tid < 64) {
    int idx = n0 + tid + 1; if (idx >= NTOK) idx = NTOK-1;
    int q = qseq[idx];
    cls_s[tid] = g_qcls[q];
    sqd_s[tid] = g_qSqd[q];
    dsc_s[tid] = g_qdisc[q];
  }
  for (int i = tid; i < 132*64; i += 256) {
    int row = i >> 6, k = i & 63;
    Ws[k*132 + row] = la_W1[i];
  }
  if (tid < 132) bs[tid] = la_b1[tid];
  for (int i = tid; i < 200; i += 256) bs2[i] = la_b2[i];
  for (int i = tid; i < 64*16; i += 256) {
    int tok = i >> 4, c = i & 15;
    float4 v = ((const float4*)(g_HS + (size_t)(n0+tok)*64))[c];
    int p = tok >> 1, e = tok & 1;
    float* base = (float*)&tp[p*66 + 4*c];
    base[0+e] = v.x; base[2+e] = v.y; base[4+e] = v.z; base[6+e] = v.w;
  }
  __syncthreads();

  float b0 = bs[lane], b1v = bs[32+lane], b2v = bs[64+lane], b3v = bs[96+lane];
  float b4v = (lane < 4) ? bs[128+lane] : 0.f;
  ull acc[4][5];
  {
    ull p0=pack2(b0,b0), p1=pack2(b1v,b1v), p2=pack2(b2v,b2v), p3=pack2(b3v,b3v), p4=pack2(b4v,b4v);
    #pragma unroll
    for (int p = 0; p < 4; p++) { acc[p][0]=p0; acc[p][1]=p1; acc[p][2]=p2; acc[p][3]=p3; acc[p][4]=p4; }
  }
  int pbase = wid*4;
  #pragma unroll 2
  for (int k2 = 0; k2 < 32; k2++) {
    int k = 2*k2;
    float wa0 = Ws[k*132 + lane];
    float wa1 = Ws[k*132 + 32 + lane];
    float wa2 = Ws[k*132 + 64 + lane];
    float wa3 = Ws[k*132 + 96 + lane];
    float wa4 = (lane < 4) ? Ws[k*132 + 128 + lane] : 0.f;
    float wb0 = Ws[(k+1)*132 + lane];
    float wb1 = Ws[(k+1)*132 + 32 + lane];
    float wb2 = Ws[(k+1)*132 + 64 + lane];
    float wb3 = Ws[(k+1)*132 + 96 + lane];
    float wb4 = (lane < 4) ? Ws[(k+1)*132 + 128 + lane] : 0.f;
    ull dA0=pack2(wa0,wa0), dA1=pack2(wa1,wa1), dA2=pack2(wa2,wa2), dA3=pack2(wa3,wa3), dA4=pack2(wa4,wa4);
    ull dB0=pack2(wb0,wb0), dB1=pack2(wb1,wb1), dB2=pack2(wb2,wb2), dB3=pack2(wb3,wb3), dB4=pack2(wb4,wb4);
    #pragma unroll
    for (int p = 0; p < 4; p++) {
      ulonglong2 hd = *(const ulonglong2*)(tp + (pbase+p)*66 + k);   // broadcast LDS.128
      acc[p][0] = ffma2(dA0, hd.x, acc[p][0]);
      acc[p][1] = ffma2(dA1, hd.x, acc[p][1]);
      acc[p][2] = ffma2(dA2, hd.x, acc[p][2]);
      acc[p][3] = ffma2(dA3, hd.x, acc[p][3]);
      acc[p][4] = ffma2(dA4, hd.x, acc[p][4]);
      acc[p][0] = ffma2(dB0, hd.y, acc[p][0]);
      acc[p][1] = ffma2(dB1, hd.y, acc[p][1]);
      acc[p][2] = ffma2(dB2, hd.y, acc[p][2]);
      acc[p][3] = ffma2(dB3, hd.y, acc[p][3]);
      acc[p][4] = ffma2(dB4, hd.y, acc[p][4]);
    }
  }

  #pragma unroll
  for (int p = 0; p < 4; p++) {
    float va[5], vb[5];
    #pragma unroll
    for (int c = 0; c < 5; c++) {
      unpack2(acc[p][c], va[c], vb[c]);
      va[c] = fmaxf(va[c], 0.f);
      vb[c] = fmaxf(vb[c], 0.f);
    }
    int lt0 = (pbase + p)*2, lt1 = lt0 + 1;
    int4 cA = cls_s[lt0], cB = cls_s[lt1];
    int carrA[4] = {cA.x, cA.y, cA.z, cA.w};
    int carrB[4] = {cB.x, cB.y, cB.z, cB.w};
    float acc8[8];
    #pragma unroll
    for (int jj = 0; jj < 4; jj++) {
      int ccA = (carrA[jj] < 0) ? 0 : carrA[jj];
      int ccB = (carrB[jj] < 0) ? 0 : carrB[jj];
      const float* rA = la_W2 + (size_t)ccA*MIDQ;
      const float* rB = la_W2 + (size_t)ccB*MIDQ;
      float aA = va[0]*rA[lane] + va[1]*rA[32+lane] + va[2]*rA[64+lane] + va[3]*rA[96+lane];
      float aB = vb[0]*rB[lane] + vb[1]*rB[32+lane] + vb[2]*rB[64+lane] + vb[3]*rB[96+lane];
      if (lane < 4) { aA += va[4]*rA[128+lane]; aB += vb[4]*rB[128+lane]; }
      acc8[jj] = aA; acc8[4+jj] = aB;
    }
    #pragma unroll
    for (int o = 16; o > 0; o >>= 1) {              // ILP-8 interleaved butterflies
      #pragma unroll
      for (int jj = 0; jj < 8; jj++) acc8[jj] += __shfl_xor_sync(0xffffffffu, acc8[jj], o);
    }
    if (lane == 0) {
      #pragma unroll
      for (int e = 0; e < 2; e++) {
        int lt = e ? lt1 : lt0;
        int n = n0 + lt;
        int bb = n / TT, it = n - bb*TT;
        if (it == TT-1) continue;
        const int* carr = e ? carrB : carrA;
        float S = 0.f;
        #pragma unroll
        for (int jj = 0; jj < 4; jj++)
          if (carr[jj] >= 0) S += fsig(acc8[e*4+jj] + bs2[carr[jj]]);
        float sq = sqd_s[lt];
        float y = dsc_s[lt]*__fdividef(S - sq, sq + 1e-6f);
        out[bb*(TT-1) + it] = fsig(y);
      }
    }
  }
}

// ---------------- launcher --------------------------------------------------
extern "C" void kernel_launch(void* const* d_in, const int* in_sizes, int n_in,
                              void* d_out, int out_size)
{
  const float* E_q    = (const float*)d_in[0];
  const float* E_c    = (const float*)d_in[1];
  const float* E_it   = (const float*)d_in[2];
  const float* E_ut   = (const float*)d_in[3];
  const float* E_nh   = (const float*)d_in[4];
  const float* W_fuse = (const float*)d_in[5];
  const float* b_fuse = (const float*)d_in[6];
  const float* W_ih   = (const float*)d_in[7];
  const float* b_ih   = (const float*)d_in[8];
  const float* W_hh   = (const float*)d_in[9];
  const float* b_hh   = (const float*)d_in[10];
  const float* qd_W1  = (const float*)d_in[11];
  const float* qd_b1  = (const float*)d_in[12];
  const float* qd_W2  = (const float*)d_in[13];
  const float* qd_b2  = (const float*)d_in[14];
  const float* la_W1  = (const float*)d_in[15];
  const float* la_b1  = (const float*)d_in[16];
  const float* la_W2  = (const float*)d_in[17];
  const float* la_b2  = (const float*)d_in[18];
  const float* dc_W1  = (const float*)d_in[19];
  const float* dc_b1  = (const float*)d_in[20];
  const float* dc_W2  = (const float*)d_in[21];
  const float* dc_b2  = (const float*)d_in[22];

  int off = (in_sizes[23] > 1000000) ? 1 : 0;
  const int* qseq  = (const int*)d_in[23+off];
  const int* cseq  = (const int*)d_in[24+off];
  const int* itseq = (const int*)d_in[25+off];
  const int* utseq = (const int*)d_in[26+off];
  const int* nhseq = (const int*)d_in[27+off];
  const int* naseq = (const int*)d_in[28+off];
  const int* q2c   = (const int*)d_in[29+off];
  const int* q2cm  = (const int*)d_in[30+off];

  const int P0_SMEM = 33024;                                // max(tq 33024, hq 32768)
  const int FOUT_SMEM = (64*132 + 134 + 202)*4 + 32*66*8;   // 52032 bytes
  cudaFuncSetAttribute(fout_kernel, cudaFuncAttributeMaxDynamicSharedMemorySize, FOUT_SMEM);

  p0_kernel<<<842, 256, P0_SMEM>>>(E_q, E_c, E_it, E_ut, E_nh,
                                   W_ih, b_ih, W_fuse, b_fuse, qd_W1, qd_b1);
  p1b_kernel<<<(NQ+7)/8, 256>>>(E_q, qd_W2, qd_b2, dc_W1, dc_b1, dc_W2, dc_b2, q2c, q2cm);
  xp_kernel<<<NTOK/32, 192>>>(qseq, cseq, itseq, utseq, nhseq, naseq);
  gru_kernel<<<BB, 64>>>(W_hh, b_hh);            // launch #4 -> profiled
  fout_kernel<<<NTOK/64, 256, FOUT_SMEM>>>(la_W1, la_b1, la_W2, la_b2, qseq, (float*)d_out);
}